// round 5
// baseline (speedup 1.0000x reference)
#include <cuda_runtime.h>
#include <cuda_bf16.h>
#include <cstdint>

#define BATCH 128
#define NN    512
#define KNB   16
#define BN    (BATCH*NN)
#define NEGS  0.01f

// ---------------- scratch (device globals; no allocation allowed) -------------
__device__ float g_xx[BN*5];
__device__ float g_x1[BN*64];
__device__ float g_x2[BN*64];
__device__ int   g_idx[BN*KNB];
__device__ float g_A[(size_t)BN*128];
__device__ float g_C[(size_t)BN*128];
__device__ float g_pool[BATCH*256];
__device__ float g_sq[BN];
__device__ float g_d2[(size_t)BN*NN];   // d2 matrix, later reused as HS buffer

// split-TF32 weight copies
__device__ float g_w1b_h[64*64],   g_w1b_l[64*64];
__device__ float g_w2b_h[128*64],  g_w2b_l[128*64];
__device__ float g_wl1_h[136*512], g_wl1_l[136*512];
__device__ float g_wl2_h[512*256], g_wl2_l[512*256];

__device__ __forceinline__ float leaky(float v){ return v > 0.f ? v : NEGS*v; }

__device__ __forceinline__ void atomicMaxFloat(float* addr, float value){
    if (value >= 0.f) atomicMax((int*)addr, __float_as_int(value));
    else              atomicMin((unsigned int*)addr, __float_as_uint(value));
}

__device__ __forceinline__ unsigned f2tf(float x){
    unsigned u; asm("cvt.rna.tf32.f32 %0, %1;" : "=r"(u) : "f"(x)); return u;
}
__device__ __forceinline__ void splt(float x, unsigned &h, unsigned &l){
    h = f2tf(x);
    l = f2tf(x - __uint_as_float(h));
}
__device__ __forceinline__ void mma8(float* c, const unsigned* a, const unsigned* b){
    asm("mma.sync.aligned.m16n8k8.row.col.f32.tf32.tf32.f32 "
        "{%0,%1,%2,%3}, {%4,%5,%6,%7}, {%8,%9}, {%0,%1,%2,%3};"
        : "+f"(c[0]), "+f"(c[1]), "+f"(c[2]), "+f"(c[3])
        : "r"(a[0]), "r"(a[1]), "r"(a[2]), "r"(a[3]), "r"(b[0]), "r"(b[1]));
}

// sortable-u32 transform: ascending uint order == ascending float order
__device__ __forceinline__ unsigned fsort(float f){
    unsigned b = __float_as_uint(f);
    return b ^ (((int)b >> 31) | 0x80000000u);
}

__device__ __forceinline__ void ce(unsigned long long &a, unsigned long long &b){
    if (b < a){ unsigned long long t = a; a = b; b = t; }
}

// warp-cooperative top-16-of-512: each lane owns 16 keys (u64: value<<32|index).
// Lane-local Batcher sort (63 CE), then 16 rounds of head-merge extraction.
__device__ __forceinline__ void warp_top16(unsigned long long* key, int lane, int* out){
    #pragma unroll
    for (int p = 1; p < 16; p <<= 1){
        #pragma unroll
        for (int k = p; k >= 1; k >>= 1){
            #pragma unroll
            for (int j = k & (p - 1); j + k < 16; j += 2*k){
                #pragma unroll
                for (int i = 0; i < k; i++){
                    if (i + j + k < 16){
                        if (((i + j)/(2*p)) == ((i + j + k)/(2*p)))
                            ce(key[i + j], key[i + j + k]);
                    }
                }
            }
        }
    }
    int mine = 0;
    #pragma unroll
    for (int r = 0; r < KNB; r++){
        unsigned long long m = key[0];
        #pragma unroll
        for (int off = 16; off; off >>= 1){
            unsigned long long o = __shfl_xor_sync(0xffffffffu, m, off);
            if (o < m) m = o;
        }
        mine = (lane == r) ? (int)(unsigned)(m & 0xffffffffu) : mine;
        if (key[0] == m){
            #pragma unroll
            for (int i = 0; i < 15; i++) key[i] = key[i+1];
            key[15] = ~0ull;
        }
    }
    if (lane < KNB) out[lane] = mine;
}

// ---------------- prep: split weights into tf32 hi/lo ------------------------
__global__ void k_prep(const float* __restrict__ w1b, const float* __restrict__ w2b,
                       const float* __restrict__ wl1, const float* __restrict__ wl2){
    int i = blockIdx.x*256 + threadIdx.x;
    float v; float *ph, *pl;
    if (i < 4096){ v = w1b[i]; ph = g_w1b_h + i; pl = g_w1b_l + i; }
    else if (i < 12288){ int j = i - 4096; v = w2b[j]; ph = g_w2b_h + j; pl = g_w2b_l + j; }
    else if (i < 81920){
        int j = i - 12288; int k = j >> 9, c = j & 511;
        v = (k < 133) ? wl1[k*512 + c] : 0.f;
        ph = g_wl1_h + j; pl = g_wl1_l + j;
    }
    else if (i < 212992){ int j = i - 81920; v = wl2[j]; ph = g_wl2_h + j; pl = g_wl2_l + j; }
    else return;
    unsigned hi = f2tf(v);
    float lo = v - __uint_as_float(hi);
    *ph = __uint_as_float(hi);
    *pl = __uint_as_float(f2tf(lo));
}

// ---------------- 0) build xx = [tq, x, pos] ---------------------------------
__global__ void k_build(const float* __restrict__ x, const float* __restrict__ pos,
                        const float* __restrict__ tq){
    int i = blockIdx.x*blockDim.x + threadIdx.x;
    if (i < BN){
        g_xx[i*5+0] = tq[i];
        g_xx[i*5+1] = x[i];
        g_xx[i*5+2] = pos[i*3+0];
        g_xx[i*5+3] = pos[i*3+1];
        g_xx[i*5+4] = pos[i*3+2];
    }
}

__global__ void k_initpool(){
    int i = blockIdx.x*blockDim.x + threadIdx.x;
    if (i < BATCH*256) g_pool[i] = __int_as_float(0xff800000); // -inf
}

// ---------------- 1a) kNN d=5: distances + fast select -----------------------
__global__ void k_knn5(){
    const int D = 5, TILE = 128, PAD = D + 1;
    __shared__ float tile[TILE*PAD];
    __shared__ float sqs[TILE];
    __shared__ float fi[8][D];
    __shared__ float fsq[8];

    int b  = blockIdx.x >> 6;
    int q0 = (blockIdx.x & 63) * 8;
    int warp = threadIdx.x >> 5, lane = threadIdx.x & 31;
    int qi = q0 + warp;
    const float* Fb = g_xx + (size_t)b*NN*D;

    for (int d = lane; d < D; d += 32) fi[warp][d] = Fb[qi*D + d];
    __syncwarp();
    if (lane == 0){
        float s = 0.f;
        #pragma unroll
        for (int d = 0; d < D; d++) s += fi[warp][d]*fi[warp][d];
        fsq[warp] = s;
    }
    __syncwarp();
    float sqi = fsq[warp];

    float d2loc[16];
    for (int t = 0; t < NN/TILE; t++){
        __syncthreads();
        for (int idx = threadIdx.x; idx < TILE*D; idx += 256){
            int r = idx / D, c = idx % D;
            tile[r*PAD + c] = Fb[(t*TILE + r)*D + c];
        }
        __syncthreads();
        if (threadIdx.x < TILE){
            float s = 0.f;
            #pragma unroll
            for (int d = 0; d < D; d++){
                float v = tile[threadIdx.x*PAD + d];
                s += v*v;
            }
            sqs[threadIdx.x] = s;
        }
        __syncthreads();
        #pragma unroll
        for (int u = 0; u < TILE/32; u++){
            int jj = u*32 + lane;
            float dot = 0.f;
            #pragma unroll
            for (int d = 0; d < D; d++) dot += fi[warp][d]*tile[jj*PAD + d];
            d2loc[t*(TILE/32) + u] = sqi + sqs[jj] - 2.f*dot;
        }
    }

    unsigned long long keys[16];
    #pragma unroll
    for (int u = 0; u < 16; u++)
        keys[u] = ((unsigned long long)fsort(d2loc[u]) << 32) | (unsigned)(u*32 + lane);
    warp_top16(keys, lane, g_idx + ((size_t)b*NN + qi)*KNB);
}

// ---------------- 1b) kNN d=64: row norms ------------------------------------
__global__ void k_sq(){
    int warp = threadIdx.x >> 5, lane = threadIdx.x & 31;
    int row = blockIdx.x*8 + warp;
    float2 v = ((const float2*)(g_x1 + (size_t)row*64))[lane];
    float s = v.x*v.x + v.y*v.y;
    #pragma unroll
    for (int off = 16; off > 0; off >>= 1) s += __shfl_xor_sync(0xffffffffu, s, off);
    if (lane == 0) g_sq[row] = s;
}

// ---------------- 1c) kNN d=64: pairwise d2 via split-TF32 mma ---------------
// 256 thr = 8 warps; block tile 128(i) x 128(j); warp tile 32 x 64; K=64 in 2x32.
__global__ void k_d2t(){
    __shared__ float As[128*36];
    __shared__ float Bs[128*36];
    int b  = blockIdx.z;
    int i0 = blockIdx.y*128, j0 = blockIdx.x*128;
    const float* Fb = g_x1 + (size_t)b*NN*64;
    int t = threadIdx.x, lane = t & 31, w = t >> 5;
    int wx = w & 1, wy = w >> 1;
    int r = lane >> 2, q = lane & 3;

    float acc[2][8][4];
    #pragma unroll
    for (int mt = 0; mt < 2; mt++)
        #pragma unroll
        for (int nt = 0; nt < 8; nt++)
            #pragma unroll
            for (int i = 0; i < 4; i++) acc[mt][nt][i] = 0.f;

    for (int kc = 0; kc < 64; kc += 32){
        __syncthreads();
        for (int i = t; i < 128*8; i += 256){
            int m = i >> 3, kq = (i & 7)*4;
            *(float4*)&As[m*36 + kq] = *(const float4*)(Fb + (i0+m)*64 + kc + kq);
            *(float4*)&Bs[m*36 + kq] = *(const float4*)(Fb + (j0+m)*64 + kc + kq);
        }
        __syncthreads();
        #pragma unroll
        for (int k0 = 0; k0 < 32; k0 += 8){
            unsigned ah[2][4], al[2][4];
            #pragma unroll
            for (int mt = 0; mt < 2; mt++){
                int row = wy*32 + mt*16;
                splt(As[(row+r)*36 + k0 + q],       ah[mt][0], al[mt][0]);
                splt(As[(row+r+8)*36 + k0 + q],     ah[mt][1], al[mt][1]);
                splt(As[(row+r)*36 + k0 + q + 4],   ah[mt][2], al[mt][2]);
                splt(As[(row+r+8)*36 + k0 + q + 4], ah[mt][3], al[mt][3]);
            }
            #pragma unroll
            for (int nt = 0; nt < 8; nt++){
                int col = wx*64 + nt*8;
                unsigned bh[2], bl[2];
                splt(Bs[(col+r)*36 + k0 + q],     bh[0], bl[0]);
                splt(Bs[(col+r)*36 + k0 + q + 4], bh[1], bl[1]);
                #pragma unroll
                for (int mt = 0; mt < 2; mt++){
                    mma8(acc[mt][nt], ah[mt], bh);
                    mma8(acc[mt][nt], ah[mt], bl);
                    mma8(acc[mt][nt], al[mt], bh);
                }
            }
        }
    }

    #pragma unroll
    for (int mt = 0; mt < 2; mt++){
        int rowb = i0 + wy*32 + mt*16;
        float si0 = g_sq[b*NN + rowb + r];
        float si1 = g_sq[b*NN + rowb + r + 8];
        #pragma unroll
        for (int nt = 0; nt < 8; nt++){
            int colb = j0 + wx*64 + nt*8 + 2*q;
            float sj0 = g_sq[b*NN + colb], sj1 = g_sq[b*NN + colb + 1];
            float2 v0, v1;
            v0.x = si0 + sj0 - 2.f*acc[mt][nt][0];
            v0.y = si0 + sj1 - 2.f*acc[mt][nt][1];
            v1.x = si1 + sj0 - 2.f*acc[mt][nt][2];
            v1.y = si1 + sj1 - 2.f*acc[mt][nt][3];
            *(float2*)(g_d2 + (size_t)(b*NN + rowb + r)*NN + colb)     = v0;
            *(float2*)(g_d2 + (size_t)(b*NN + rowb + r + 8)*NN + colb) = v1;
        }
    }
}

// ---------------- 1d) kNN d=64: fast top-16 select ---------------------------
__global__ void k_select(){
    int warp = threadIdx.x >> 5, lane = threadIdx.x & 31;
    int node = blockIdx.x*8 + warp;
    const float* row = g_d2 + (size_t)node*NN;
    unsigned long long keys[16];
    #pragma unroll
    for (int u4 = 0; u4 < 4; u4++){
        float4 x = *(const float4*)(row + lane*16 + u4*4);
        int j0 = lane*16 + u4*4;
        keys[u4*4+0] = ((unsigned long long)fsort(x.x) << 32) | (unsigned)(j0+0);
        keys[u4*4+1] = ((unsigned long long)fsort(x.y) << 32) | (unsigned)(j0+1);
        keys[u4*4+2] = ((unsigned long long)fsort(x.z) << 32) | (unsigned)(j0+2);
        keys[u4*4+3] = ((unsigned long long)fsort(x.w) << 32) | (unsigned)(j0+3);
    }
    warp_top16(keys, lane, g_idx + (size_t)node*KNB);
}

// ---------------- 2a) conv1 layer-1 factorization (d=5, H=64) ----------------
__global__ void k_convA1(const float* __restrict__ W, const float* __restrict__ bias){
    int t = blockIdx.x*blockDim.x + threadIdx.x;
    if (t >= BN*64) return;
    int i = t >> 6, c = t & 63;
    const float* f = g_xx + (size_t)i*5;
    float a = bias[c], cc = 0.f;
    #pragma unroll
    for (int d = 0; d < 5; d++){
        float v  = f[d];
        float wt = W[d*64 + c];
        float wb = W[(5 + d)*64 + c];
        a  += v*(wt - wb);
        cc += v*wb;
    }
    g_A[(size_t)i*64 + c] = a;
    g_C[(size_t)i*64 + c] = cc;
}

// ---------------- 2b) conv2 layer-1 (d=64, H=128) ----------------------------
__global__ void k_convA2(const float* __restrict__ W, const float* __restrict__ bias){
    __shared__ float Wd[32*128];
    __shared__ float Wb[32*128];
    __shared__ float Fs[16*64];
    int t = threadIdx.x;
    int base = blockIdx.x*16;

    for (int idx = t; idx < 1024; idx += 256)
        Fs[idx] = g_x1[(size_t)base*64 + idx];

    int m  = t >> 4;
    int cg = (t & 15)*8;
    float a[8], cc[8];
    float4 bb0 = *(const float4*)(bias + cg);
    float4 bb1 = *(const float4*)(bias + cg + 4);
    a[0]=bb0.x; a[1]=bb0.y; a[2]=bb0.z; a[3]=bb0.w;
    a[4]=bb1.x; a[5]=bb1.y; a[6]=bb1.z; a[7]=bb1.w;
    #pragma unroll
    for (int q = 0; q < 8; q++) cc[q] = 0.f;

    for (int db = 0; db < 64; db += 32){
        __syncthreads();
        for (int idx = t; idx < 4096; idx += 256){
            int d = idx >> 7, c = idx & 127;
            float wt = W[(db + d)*128 + c];
            float wb = W[(64 + db + d)*128 + c];
            Wd[idx] = wt - wb;
            Wb[idx] = wb;
        }
        __syncthreads();
        #pragma unroll 4
        for (int d = 0; d < 32; d++){
            float v = Fs[m*64 + db + d];
            float4 w0 = *(const float4*)&Wd[d*128 + cg];
            float4 w1 = *(const float4*)&Wd[d*128 + cg + 4];
            float4 u0 = *(const float4*)&Wb[d*128 + cg];
            float4 u1 = *(const float4*)&Wb[d*128 + cg + 4];
            a[0] += v*w0.x; a[1] += v*w0.y; a[2] += v*w0.z; a[3] += v*w0.w;
            a[4] += v*w1.x; a[5] += v*w1.y; a[6] += v*w1.z; a[7] += v*w1.w;
            cc[0] += v*u0.x; cc[1] += v*u0.y; cc[2] += v*u0.z; cc[3] += v*u0.w;
            cc[4] += v*u1.x; cc[5] += v*u1.y; cc[6] += v*u1.z; cc[7] += v*u1.w;
        }
    }
    int node = base + m;
    float4* pa = (float4*)(g_A + (size_t)node*128 + cg);
    float4* pc = (float4*)(g_C + (size_t)node*128 + cg);
    pa[0] = make_float4(a[0],a[1],a[2],a[3]);
    pa[1] = make_float4(a[4],a[5],a[6],a[7]);
    pc[0] = make_float4(cc[0],cc[1],cc[2],cc[3]);
    pc[1] = make_float4(cc[4],cc[5],cc[6],cc[7]);
}

// ---------------- 3) edge MLP layer-2 + max over K — tensor cores ------------
template<int H>
__global__ void k_edge2t(const float* __restrict__ bias){
    const int S = (H == 128) ? 132 : 68;
    __shared__ float hs[4*16*S];
    __shared__ float wsh[16*72];
    __shared__ float wsl[16*72];
    int t = threadIdx.x, warp = t >> 5, lane = t & 31;
    int node = blockIdx.x*4 + warp;
    int b = node / NN;
    float* hw = hs + warp*16*S;
    float* out = (H == 64) ? g_x1 : g_x2;
    const float* Wh = (H == 64) ? g_w1b_h : g_w2b_h;
    const float* Wl = (H == 64) ? g_w1b_l : g_w2b_l;

    int jv = 0;
    if (lane < 16) jv = g_idx[(size_t)node*KNB + lane];

    if (H == 128){
        float4 a4 = *(const float4*)(g_A + (size_t)node*128 + lane*4);
        #pragma unroll 4
        for (int m = 0; m < 16; m++){
            int j = b*NN + __shfl_sync(0xffffffffu, jv, m);
            float4 c4 = *(const float4*)(g_C + (size_t)j*128 + lane*4);
            float4 h;
            h.x = leaky(a4.x + c4.x); h.y = leaky(a4.y + c4.y);
            h.z = leaky(a4.z + c4.z); h.w = leaky(a4.w + c4.w);
            *(float4*)&hw[m*S + lane*4] = h;
        }
    } else {
        float2 a2 = *(const float2*)(g_A + (size_t)node*64 + lane*2);
        #pragma unroll 4
        for (int m = 0; m < 16; m++){
            int j = b*NN + __shfl_sync(0xffffffffu, jv, m);
            float2 c2 = *(const float2*)(g_C + (size_t)j*64 + lane*2);
            float2 h;
            h.x = leaky(a2.x + c2.x); h.y = leaky(a2.y + c2.y);
            *(float2*)&hw[m*S + lane*2] = h;
        }
    }
    __syncwarp();

    float acc[8][4];
    #pragma unroll
    for (int nt = 0; nt < 8; nt++)
        #pragma unroll
        for (int i = 0; i < 4; i++) acc[nt][i] = 0.f;

    int r = lane >> 2, q = lane & 3;
    for (int kb = 0; kb < H; kb += 16){
        __syncthreads();
        for (int i = t; i < 1024; i += 128){
            int rr = i >> 6, c = i & 63;
            wsh[rr*72 + c] = Wh[(kb + rr)*64 + c];
            wsl[rr*72 + c] = Wl[(kb + rr)*64 + c];
        }
        __syncthreads();
        #pragma unroll
        for (int ks = 0; ks < 16; ks += 8){
            int k0 = kb + ks;
            unsigned ah[4], al[4];
            splt(hw[r*S + k0 + q],           ah[0], al[0]);
            splt(hw[(r+8)*S + k0 + q],       ah[1], al[1]);
            splt(hw[r*S + k0 + q + 4],       ah[2], al[2]);
            splt(hw[(r+8)*S + k0 + q + 4],   ah[3], al[3]);
            #pragma unroll
            for (int nt = 0; nt < 8; nt++){
                int bo = (ks + q)*72 + nt*8 + r;
                unsigned bh[2] = {__float_as_uint(wsh[bo]), __float_as_uint(wsh[bo + 288])};
                unsigned bl[2] = {__float_as_uint(wsl[bo]), __float_as_uint(wsl[bo + 288])};
                mma8(acc[nt], ah, bh);
                mma8(acc[nt], ah, bl);
                mma8(acc[nt], al, bh);
            }
        }
    }

    #pragma unroll
    for (int nt = 0; nt < 8; nt++){
        float m0 = fmaxf(acc[nt][0], acc[nt][2]);
        float m1 = fmaxf(acc[nt][1], acc[nt][3]);
        #pragma unroll
        for (int off = 4; off < 32; off <<= 1){
            m0 = fmaxf(m0, __shfl_xor_sync(0xffffffffu, m0, off));
            m1 = fmaxf(m1, __shfl_xor_sync(0xffffffffu, m1, off));
        }
        if (lane < 4){
            int c = nt*8 + lane*2;
            out[(size_t)node*64 + c]     = leaky(m0 + __ldg(bias + c));
            out[(size_t)node*64 + c + 1] = leaky(m1 + __ldg(bias + c + 1));
        }
    }
}

// ---------------- 4a) lin1: [BN x 136] @ [136 x 512] + leaky -> g_d2 ---------
__global__ void k_lin1(const float* __restrict__ bl1){
    __shared__ float CS[64*140];
    int t = threadIdx.x, lane = t & 31, w = t >> 5;
    int base = blockIdx.x*64;
    for (int i = t; i < 64*136; i += 256){
        int m = i / 136, d = i - m*136;
        int node = base + m;
        float v = 0.f;
        if (d < 5)        v = g_xx[node*5 + d];
        else if (d < 69)  v = g_x1[(size_t)node*64 + d - 5];
        else if (d < 133) v = g_x2[(size_t)node*64 + d - 69];
        CS[m*140 + d] = v;
    }
    __syncthreads();

    int r = lane >> 2, q = lane & 3;
    int n0 = w*64;
    for (int np = 0; np < 2; np++){
        float acc[4][4][4];
        #pragma unroll
        for (int mt = 0; mt < 4; mt++)
            #pragma unroll
            for (int nt = 0; nt < 4; nt++)
                #pragma unroll
                for (int i = 0; i < 4; i++) acc[mt][nt][i] = 0.f;

        for (int k0 = 0; k0 < 136; k0 += 8){
            unsigned ah[4][4], al[4][4];
            #pragma unroll
            for (int mt = 0; mt < 4; mt++){
                int rb = mt*16;
                splt(CS[(rb+r)*140 + k0 + q],         ah[mt][0], al[mt][0]);
                splt(CS[(rb+r+8)*140 + k0 + q],       ah[mt][1], al[mt][1]);
                splt(CS[(rb+r)*140 + k0 + q + 4],     ah[mt][2], al[mt][2]);
                splt(CS[(rb+r+8)*140 + k0 + q + 4],   ah[mt][3], al[mt][3]);
            }
            #pragma unroll
            for (int nt = 0; nt < 4; nt++){
                int col = n0 + (np*4 + nt)*8 + r;
                int o = (k0 + q)*512 + col;
                unsigned bh[2] = {__float_as_uint(__ldg(g_wl1_h + o)),
                                  __float_as_uint(__ldg(g_wl1_h + o + 2048))};
                unsigned bl[2] = {__float_as_uint(__ldg(g_wl1_l + o)),
                                  __float_as_uint(__ldg(g_wl1_l + o + 2048))};
                #pragma unroll
                for (int mt = 0; mt < 4; mt++){
                    mma8(acc[mt][nt], ah[mt], bh);
                    mma8(acc[mt][nt], ah[mt], bl);
                    mma8(acc[mt][nt], al[mt], bh);
                }
            }
        }
        #pragma unroll
        for (int mt = 0; mt < 4; mt++){
            #pragma unroll
            for (int nt = 0; nt < 4; nt++){
                int node = base + mt*16 + r;
                int col = n0 + (np*4 + nt)*8 + q*2;
                float b0 = __ldg(bl1 + col), b1 = __ldg(bl1 + col + 1);
                float2 u0, u1;
                u0.x = leaky(acc[mt][nt][0] + b0); u0.y = leaky(acc[mt][nt][1] + b1);
                u1.x = leaky(acc[mt][nt][2] + b0); u1.y = leaky(acc[mt][nt][3] + b1);
                *(float2*)(g_d2 + (size_t)node*512 + col)     = u0;
                *(float2*)(g_d2 + (size_t)(node+8)*512 + col) = u1;
            }
        }
    }
}

// ---------------- 4b) lin2: [BN x 512] @ [512 x 256] + max-pool --------------
__global__ void k_lin2(const float* __restrict__ bl2){
    __shared__ float As[64*68];
    int t = threadIdx.x, lane = t & 31, w = t >> 5;
    int base = blockIdx.x*64;
    int g = base / NN;
    int r = lane >> 2, q = lane & 3;
    int n0 = w*32;

    float acc[4][4][4];
    #pragma unroll
    for (int mt = 0; mt < 4; mt++)
        #pragma unroll
        for (int nt = 0; nt < 4; nt++)
            #pragma unroll
            for (int i = 0; i < 4; i++) acc[mt][nt][i] = 0.f;

    for (int kc = 0; kc < 512; kc += 64){
        __syncthreads();
        for (int i = t; i < 1024; i += 256){
            int m = i >> 4, kq = (i & 15)*4;
            float4 v = *(const float4*)(g_d2 + (size_t)(base + m)*512 + kc + kq);
            *(float4*)&As[m*68 + kq] = v;
        }
        __syncthreads();
        #pragma unroll
        for (int ks = 0; ks < 64; ks += 8){
            unsigned ah[4][4], al[4][4];
            #pragma unroll
            for (int mt = 0; mt < 4; mt++){
                int rb = mt*16;
                splt(As[(rb+r)*68 + ks + q],         ah[mt][0], al[mt][0]);
                splt(As[(rb+r+8)*68 + ks + q],       ah[mt][1], al[mt][1]);
                splt(As[(rb+r)*68 + ks + q + 4],     ah[mt][2], al[mt][2]);
                splt(As[(rb+r+8)*68 + ks + q + 4],   ah[mt][3], al[mt][3]);
            }
            #pragma unroll
            for (int nt = 0; nt < 4; nt++){
                int col = n0 + nt*8 + r;
                int o = (kc + ks + q)*256 + col;
                unsigned bh[2] = {__float_as_uint(__ldg(g_wl2_h + o)),
                                  __float_as_uint(__ldg(g_wl2_h + o + 1024))};
                unsigned bl[2] = {__float_as_uint(__ldg(g_wl2_l + o)),
                                  __float_as_uint(__ldg(g_wl2_l + o + 1024))};
                #pragma unroll
                for (int mt = 0; mt < 4; mt++){
                    mma8(acc[mt][nt], ah[mt], bh);
                    mma8(acc[mt][nt], ah[mt], bl);
                    mma8(acc[mt][nt], al[mt], bh);
                }
            }
        }
    }

    #pragma unroll
    for (int nt = 0; nt < 4; nt++){
        float m0 = -3.4e38f, m1 = -3.4e38f;
        #pragma unroll
        for (int mt = 0; mt < 4; mt++){
            m0 = fmaxf(m0, fmaxf(acc[mt][nt][0], acc[mt][nt][2]));
            m1 = fmaxf(m1, fmaxf(acc[mt][nt][1], acc[mt][nt][3]));
        }
        #pragma unroll
        for (int off = 4; off < 32; off <<= 1){
            m0 = fmaxf(m0, __shfl_xor_sync(0xffffffffu, m0, off));
            m1 = fmaxf(m1, __shfl_xor_sync(0xffffffffu, m1, off));
        }
        if (lane < 4){
            int col = n0 + nt*8 + lane*2;
            atomicMaxFloat(&g_pool[g*256 + col],     m0 + __ldg(bl2 + col));
            atomicMaxFloat(&g_pool[g*256 + col + 1], m1 + __ldg(bl2 + col + 1));
        }
    }
}

// ---------------- 5) head: leaky -> 256x128 -> leaky -> 128x3 ----------------
__global__ void k_head(const float* __restrict__ wm1, const float* __restrict__ bm1,
                       const float* __restrict__ wm2, const float* __restrict__ bm2,
                       float* __restrict__ out){
    __shared__ float gs[256];
    __shared__ float ms[128];
    int b = blockIdx.x, t = threadIdx.x;
    for (int c = t; c < 256; c += 128) gs[c] = leaky(g_pool[b*256 + c]);
    __syncthreads();
    float acc = bm1[t];
    #pragma unroll 8
    for (int d = 0; d < 256; d++) acc += gs[d]*wm1[d*128 + t];
    ms[t] = leaky(acc);
    __syncthreads();
    if (t < 3){
        float o = bm2[t];
        #pragma unroll 8
        for (int d = 0; d < 128; d++) o += ms[d]*wm2[d*3 + t];
        out[b*3 + t] = o;
    }
}

// -----------------------------------------------------------------------------
extern "C" void kernel_launch(void* const* d_in, const int* in_sizes, int n_in,
                              void* d_out, int out_size){
    const float* x   = (const float*)d_in[0];
    const float* pos = (const float*)d_in[1];
    const float* tq  = (const float*)d_in[2];
    const float* w1a = (const float*)d_in[4];
    const float* b1a = (const float*)d_in[5];
    const float* w1b = (const float*)d_in[6];
    const float* b1b = (const float*)d_in[7];
    const float* w2a = (const float*)d_in[8];
    const float* b2a = (const float*)d_in[9];
    const float* w2b = (const float*)d_in[10];
    const float* b2b = (const float*)d_in[11];
    const float* wl1 = (const float*)d_in[12];
    const float* bl1 = (const float*)d_in[13];
    const float* wl2 = (const float*)d_in[14];
    const float* bl2 = (const float*)d_in[15];
    const float* wm1 = (const float*)d_in[16];
    const float* bm1 = (const float*)d_in[17];
    const float* wm2 = (const float*)d_in[18];
    const float* bm2 = (const float*)d_in[19];
    float* out = (float*)d_out;

    k_prep<<<832, 256>>>(w1b, w2b, wl1, wl2);
    k_build<<<BN/256, 256>>>(x, pos, tq);
    k_initpool<<<(BATCH*256)/256, 256>>>();

    // conv1
    k_knn5<<<BATCH*(NN/8), 256>>>();
    k_convA1<<<(BN*64)/256, 256>>>(w1a, b1a);
    k_edge2t<64><<<BN/4, 128>>>(b1b);

    // conv2
    k_sq<<<BN/8, 256>>>();
    {
        dim3 grid(4, 4, BATCH);
        k_d2t<<<grid, 256>>>();
    }
    k_select<<<BN/8, 256>>>();
    k_convA2<<<BN/16, 256>>>(w2a, b2a);
    k_edge2t<128><<<BN/4, 128>>>(b2b);

    // lin1 -> g_d2 (HS), lin2 + fused pool, head
    k_lin1<<<BN/64, 256>>>(bl1);
    k_lin2<<<BN/64, 256>>>(bl2);
    k_head<<<BATCH, 128>>>(wm1, bm1, wm2, bm2, out);
}

// round 6
// speedup vs baseline: 1.2859x; 1.2859x over previous
#include <cuda_runtime.h>
#include <cuda_bf16.h>
#include <cstdint>

#define BATCH 128
#define NN    512
#define KNB   16
#define BN    (BATCH*NN)
#define NEGS  0.01f

// ---------------- scratch (device globals; no allocation allowed) -------------
__device__ float g_xx[BN*5];
__device__ float g_x1[BN*64];
__device__ float g_x2[BN*64];
__device__ int   g_idx[BN*KNB];
__device__ float g_A[(size_t)BN*128];
__device__ float g_C[(size_t)BN*128];
__device__ float g_pool[BATCH*256];
__device__ float g_sq[BN];
__device__ float g_d2[(size_t)BN*NN];   // d2 matrix, later reused as HS buffer

// split-TF32 weight copies
__device__ float g_w1b_h[64*64],   g_w1b_l[64*64];
__device__ float g_w2b_h[128*64],  g_w2b_l[128*64];
__device__ float g_wl1_h[136*512], g_wl1_l[136*512];
__device__ float g_wl2_h[512*256], g_wl2_l[512*256];

__device__ __forceinline__ float leaky(float v){ return v > 0.f ? v : NEGS*v; }

__device__ __forceinline__ void atomicMaxFloat(float* addr, float value){
    if (value >= 0.f) atomicMax((int*)addr, __float_as_int(value));
    else              atomicMin((unsigned int*)addr, __float_as_uint(value));
}

__device__ __forceinline__ unsigned f2tf(float x){
    unsigned u; asm("cvt.rna.tf32.f32 %0, %1;" : "=r"(u) : "f"(x)); return u;
}
__device__ __forceinline__ void splt(float x, unsigned &h, unsigned &l){
    h = f2tf(x);
    l = f2tf(x - __uint_as_float(h));
}
__device__ __forceinline__ void mma8(float* c, const unsigned* a, const unsigned* b){
    asm("mma.sync.aligned.m16n8k8.row.col.f32.tf32.tf32.f32 "
        "{%0,%1,%2,%3}, {%4,%5,%6,%7}, {%8,%9}, {%0,%1,%2,%3};"
        : "+f"(c[0]), "+f"(c[1]), "+f"(c[2]), "+f"(c[3])
        : "r"(a[0]), "r"(a[1]), "r"(a[2]), "r"(a[3]), "r"(b[0]), "r"(b[1]));
}

// sortable-u32 transform: ascending uint order == ascending float order
__device__ __forceinline__ unsigned fsort(float f){
    unsigned b = __float_as_uint(f);
    return b ^ (((int)b >> 31) | 0x80000000u);
}

// warp-cooperative exact top-16-of-512 with lower-index tiebreak.
// Each lane owns v[0..15]; global index of slot u is (LANEMAJOR ? lane*16+u : u*32+lane).
// Lane caches its sorted smallest-4 as u64 keys (val<<32|idx); per round: warp
// u64 shuffle-min, winner pops head; refill-by-rescan only when cache empties.
template<bool LANEMAJOR>
__device__ __forceinline__ void sel16(const float* v, int lane, int* out){
    const unsigned long long INF = ~0ull;
    unsigned long long s0 = INF, s1 = INF, s2 = INF, s3 = INF;
    #pragma unroll
    for (int u = 0; u < 16; u++){
        int j = LANEMAJOR ? (lane*16 + u) : (u*32 + lane);
        unsigned long long k = ((unsigned long long)fsort(v[u]) << 32) | (unsigned)j;
        if (k < s3){
            s3 = k;
            if (s3 < s2){ unsigned long long t = s2; s2 = s3; s3 = t; }
            if (s2 < s1){ unsigned long long t = s1; s1 = s2; s2 = t; }
            if (s1 < s0){ unsigned long long t = s0; s0 = s1; s1 = t; }
        }
    }
    unsigned mask = 0;   // consumed slots of this lane
    int mine = 0;
    #pragma unroll 1
    for (int r = 0; r < KNB; r++){
        unsigned long long m = s0;
        #pragma unroll
        for (int off = 16; off; off >>= 1){
            unsigned long long o = __shfl_xor_sync(0xffffffffu, m, off);
            if (o < m) m = o;
        }
        if (lane == r) mine = (int)(unsigned)(m & 0xffffffffu);
        if (s0 == m){   // unique keys -> exactly one winning lane
            int j = (int)(unsigned)(m & 0xffffffffu);
            int u = LANEMAJOR ? (j & 15) : (j >> 5);
            mask |= 1u << u;
            s0 = s1; s1 = s2; s2 = s3; s3 = INF;
            if (s0 == INF && mask != 0xffffu){
                #pragma unroll
                for (int u2 = 0; u2 < 16; u2++){
                    if (!((mask >> u2) & 1u)){
                        int j2 = LANEMAJOR ? (lane*16 + u2) : (u2*32 + lane);
                        unsigned long long k = ((unsigned long long)fsort(v[u2]) << 32) | (unsigned)j2;
                        if (k < s3){
                            s3 = k;
                            if (s3 < s2){ unsigned long long t = s2; s2 = s3; s3 = t; }
                            if (s2 < s1){ unsigned long long t = s1; s1 = s2; s2 = t; }
                            if (s1 < s0){ unsigned long long t = s0; s0 = s1; s1 = t; }
                        }
                    }
                }
            }
        }
    }
    if (lane < KNB) out[lane] = mine;
}

// ---------------- prep: split weights into tf32 hi/lo ------------------------
__global__ void k_prep(const float* __restrict__ w1b, const float* __restrict__ w2b,
                       const float* __restrict__ wl1, const float* __restrict__ wl2){
    int i = blockIdx.x*256 + threadIdx.x;
    float v; float *ph, *pl;
    if (i < 4096){ v = w1b[i]; ph = g_w1b_h + i; pl = g_w1b_l + i; }
    else if (i < 12288){ int j = i - 4096; v = w2b[j]; ph = g_w2b_h + j; pl = g_w2b_l + j; }
    else if (i < 81920){
        int j = i - 12288; int k = j >> 9, c = j & 511;
        v = (k < 133) ? wl1[k*512 + c] : 0.f;
        ph = g_wl1_h + j; pl = g_wl1_l + j;
    }
    else if (i < 212992){ int j = i - 81920; v = wl2[j]; ph = g_wl2_h + j; pl = g_wl2_l + j; }
    else return;
    unsigned hi = f2tf(v);
    float lo = v - __uint_as_float(hi);
    *ph = __uint_as_float(hi);
    *pl = __uint_as_float(f2tf(lo));
}

// ---------------- 0) build xx = [tq, x, pos] ---------------------------------
__global__ void k_build(const float* __restrict__ x, const float* __restrict__ pos,
                        const float* __restrict__ tq){
    int i = blockIdx.x*blockDim.x + threadIdx.x;
    if (i < BN){
        g_xx[i*5+0] = tq[i];
        g_xx[i*5+1] = x[i];
        g_xx[i*5+2] = pos[i*3+0];
        g_xx[i*5+3] = pos[i*3+1];
        g_xx[i*5+4] = pos[i*3+2];
    }
}

__global__ void k_initpool(){
    int i = blockIdx.x*blockDim.x + threadIdx.x;
    if (i < BATCH*256) g_pool[i] = __int_as_float(0xff800000); // -inf
}

// ---------------- 1a) kNN d=5: distances + cached-top4 select ----------------
__global__ void k_knn5(){
    const int D = 5, TILE = 128, PAD = D + 1;
    __shared__ float tile[TILE*PAD];
    __shared__ float sqs[TILE];
    __shared__ float fi[8][D];
    __shared__ float fsq[8];

    int b  = blockIdx.x >> 6;
    int q0 = (blockIdx.x & 63) * 8;
    int warp = threadIdx.x >> 5, lane = threadIdx.x & 31;
    int qi = q0 + warp;
    const float* Fb = g_xx + (size_t)b*NN*D;

    for (int d = lane; d < D; d += 32) fi[warp][d] = Fb[qi*D + d];
    __syncwarp();
    if (lane == 0){
        float s = 0.f;
        #pragma unroll
        for (int d = 0; d < D; d++) s += fi[warp][d]*fi[warp][d];
        fsq[warp] = s;
    }
    __syncwarp();
    float sqi = fsq[warp];

    float d2loc[16];
    for (int t = 0; t < NN/TILE; t++){
        __syncthreads();
        for (int idx = threadIdx.x; idx < TILE*D; idx += 256){
            int r = idx / D, c = idx % D;
            tile[r*PAD + c] = Fb[(t*TILE + r)*D + c];
        }
        __syncthreads();
        if (threadIdx.x < TILE){
            float s = 0.f;
            #pragma unroll
            for (int d = 0; d < D; d++){
                float v = tile[threadIdx.x*PAD + d];
                s += v*v;
            }
            sqs[threadIdx.x] = s;
        }
        __syncthreads();
        #pragma unroll
        for (int u = 0; u < TILE/32; u++){
            int jj = u*32 + lane;
            float dot = 0.f;
            #pragma unroll
            for (int d = 0; d < D; d++) dot += fi[warp][d]*tile[jj*PAD + d];
            d2loc[t*(TILE/32) + u] = sqi + sqs[jj] - 2.f*dot;
        }
    }

    sel16<false>(d2loc, lane, g_idx + ((size_t)b*NN + qi)*KNB);
}

// ---------------- 1b) kNN d=64: row norms ------------------------------------
__global__ void k_sq(){
    int warp = threadIdx.x >> 5, lane = threadIdx.x & 31;
    int row = blockIdx.x*8 + warp;
    float2 v = ((const float2*)(g_x1 + (size_t)row*64))[lane];
    float s = v.x*v.x + v.y*v.y;
    #pragma unroll
    for (int off = 16; off > 0; off >>= 1) s += __shfl_xor_sync(0xffffffffu, s, off);
    if (lane == 0) g_sq[row] = s;
}

// ---------------- 1c) kNN d=64: pairwise d2 via split-TF32 mma ---------------
__global__ void k_d2t(){
    __shared__ float As[128*36];
    __shared__ float Bs[128*36];
    int b  = blockIdx.z;
    int i0 = blockIdx.y*128, j0 = blockIdx.x*128;
    const float* Fb = g_x1 + (size_t)b*NN*64;
    int t = threadIdx.x, lane = t & 31, w = t >> 5;
    int wx = w & 1, wy = w >> 1;
    int r = lane >> 2, q = lane & 3;

    float acc[2][8][4];
    #pragma unroll
    for (int mt = 0; mt < 2; mt++)
        #pragma unroll
        for (int nt = 0; nt < 8; nt++)
            #pragma unroll
            for (int i = 0; i < 4; i++) acc[mt][nt][i] = 0.f;

    for (int kc = 0; kc < 64; kc += 32){
        __syncthreads();
        for (int i = t; i < 128*8; i += 256){
            int m = i >> 3, kq = (i & 7)*4;
            *(float4*)&As[m*36 + kq] = *(const float4*)(Fb + (i0+m)*64 + kc + kq);
            *(float4*)&Bs[m*36 + kq] = *(const float4*)(Fb + (j0+m)*64 + kc + kq);
        }
        __syncthreads();
        #pragma unroll
        for (int k0 = 0; k0 < 32; k0 += 8){
            unsigned ah[2][4], al[2][4];
            #pragma unroll
            for (int mt = 0; mt < 2; mt++){
                int row = wy*32 + mt*16;
                splt(As[(row+r)*36 + k0 + q],       ah[mt][0], al[mt][0]);
                splt(As[(row+r+8)*36 + k0 + q],     ah[mt][1], al[mt][1]);
                splt(As[(row+r)*36 + k0 + q + 4],   ah[mt][2], al[mt][2]);
                splt(As[(row+r+8)*36 + k0 + q + 4], ah[mt][3], al[mt][3]);
            }
            #pragma unroll
            for (int nt = 0; nt < 8; nt++){
                int col = wx*64 + nt*8;
                unsigned bh[2], bl[2];
                splt(Bs[(col+r)*36 + k0 + q],     bh[0], bl[0]);
                splt(Bs[(col+r)*36 + k0 + q + 4], bh[1], bl[1]);
                #pragma unroll
                for (int mt = 0; mt < 2; mt++){
                    mma8(acc[mt][nt], ah[mt], bh);
                    mma8(acc[mt][nt], ah[mt], bl);
                    mma8(acc[mt][nt], al[mt], bh);
                }
            }
        }
    }

    #pragma unroll
    for (int mt = 0; mt < 2; mt++){
        int rowb = i0 + wy*32 + mt*16;
        float si0 = g_sq[b*NN + rowb + r];
        float si1 = g_sq[b*NN + rowb + r + 8];
        #pragma unroll
        for (int nt = 0; nt < 8; nt++){
            int colb = j0 + wx*64 + nt*8 + 2*q;
            float sj0 = g_sq[b*NN + colb], sj1 = g_sq[b*NN + colb + 1];
            float2 v0, v1;
            v0.x = si0 + sj0 - 2.f*acc[mt][nt][0];
            v0.y = si0 + sj1 - 2.f*acc[mt][nt][1];
            v1.x = si1 + sj0 - 2.f*acc[mt][nt][2];
            v1.y = si1 + sj1 - 2.f*acc[mt][nt][3];
            *(float2*)(g_d2 + (size_t)(b*NN + rowb + r)*NN + colb)     = v0;
            *(float2*)(g_d2 + (size_t)(b*NN + rowb + r + 8)*NN + colb) = v1;
        }
    }
}

// ---------------- 1d) kNN d=64: cached-top4 select ---------------------------
__global__ void k_select(){
    int warp = threadIdx.x >> 5, lane = threadIdx.x & 31;
    int node = blockIdx.x*8 + warp;
    const float* row = g_d2 + (size_t)node*NN;
    float v[16];
    #pragma unroll
    for (int u4 = 0; u4 < 4; u4++){
        float4 x = *(const float4*)(row + lane*16 + u4*4);
        v[u4*4+0] = x.x; v[u4*4+1] = x.y; v[u4*4+2] = x.z; v[u4*4+3] = x.w;
    }
    sel16<true>(v, lane, g_idx + (size_t)node*KNB);
}

// ---------------- 2a) conv1 layer-1 factorization (d=5, H=64) ----------------
__global__ void k_convA1(const float* __restrict__ W, const float* __restrict__ bias){
    int t = blockIdx.x*blockDim.x + threadIdx.x;
    if (t >= BN*64) return;
    int i = t >> 6, c = t & 63;
    const float* f = g_xx + (size_t)i*5;
    float a = bias[c], cc = 0.f;
    #pragma unroll
    for (int d = 0; d < 5; d++){
        float v  = f[d];
        float wt = W[d*64 + c];
        float wb = W[(5 + d)*64 + c];
        a  += v*(wt - wb);
        cc += v*wb;
    }
    g_A[(size_t)i*64 + c] = a;
    g_C[(size_t)i*64 + c] = cc;
}

// ---------------- 2b) conv2 layer-1 (d=64, H=128) ----------------------------
__global__ void k_convA2(const float* __restrict__ W, const float* __restrict__ bias){
    __shared__ float Wd[32*128];
    __shared__ float Wb[32*128];
    __shared__ float Fs[16*64];
    int t = threadIdx.x;
    int base = blockIdx.x*16;

    for (int idx = t; idx < 1024; idx += 256)
        Fs[idx] = g_x1[(size_t)base*64 + idx];

    int m  = t >> 4;
    int cg = (t & 15)*8;
    float a[8], cc[8];
    float4 bb0 = *(const float4*)(bias + cg);
    float4 bb1 = *(const float4*)(bias + cg + 4);
    a[0]=bb0.x; a[1]=bb0.y; a[2]=bb0.z; a[3]=bb0.w;
    a[4]=bb1.x; a[5]=bb1.y; a[6]=bb1.z; a[7]=bb1.w;
    #pragma unroll
    for (int q = 0; q < 8; q++) cc[q] = 0.f;

    for (int db = 0; db < 64; db += 32){
        __syncthreads();
        for (int idx = t; idx < 4096; idx += 256){
            int d = idx >> 7, c = idx & 127;
            float wt = W[(db + d)*128 + c];
            float wb = W[(64 + db + d)*128 + c];
            Wd[idx] = wt - wb;
            Wb[idx] = wb;
        }
        __syncthreads();
        #pragma unroll 4
        for (int d = 0; d < 32; d++){
            float v = Fs[m*64 + db + d];
            float4 w0 = *(const float4*)&Wd[d*128 + cg];
            float4 w1 = *(const float4*)&Wd[d*128 + cg + 4];
            float4 u0 = *(const float4*)&Wb[d*128 + cg];
            float4 u1 = *(const float4*)&Wb[d*128 + cg + 4];
            a[0] += v*w0.x; a[1] += v*w0.y; a[2] += v*w0.z; a[3] += v*w0.w;
            a[4] += v*w1.x; a[5] += v*w1.y; a[6] += v*w1.z; a[7] += v*w1.w;
            cc[0] += v*u0.x; cc[1] += v*u0.y; cc[2] += v*u0.z; cc[3] += v*u0.w;
            cc[4] += v*u1.x; cc[5] += v*u1.y; cc[6] += v*u1.z; cc[7] += v*u1.w;
        }
    }
    int node = base + m;
    float4* pa = (float4*)(g_A + (size_t)node*128 + cg);
    float4* pc = (float4*)(g_C + (size_t)node*128 + cg);
    pa[0] = make_float4(a[0],a[1],a[2],a[3]);
    pa[1] = make_float4(a[4],a[5],a[6],a[7]);
    pc[0] = make_float4(cc[0],cc[1],cc[2],cc[3]);
    pc[1] = make_float4(cc[4],cc[5],cc[6],cc[7]);
}

// ---------------- 3) edge MLP layer-2 + max over K — tensor cores ------------
template<int H>
__global__ void k_edge2t(const float* __restrict__ bias){
    const int S = (H == 128) ? 132 : 68;
    __shared__ float hs[4*16*S];
    __shared__ float wsh[16*72];
    __shared__ float wsl[16*72];
    int t = threadIdx.x, warp = t >> 5, lane = t & 31;
    int node = blockIdx.x*4 + warp;
    int b = node / NN;
    float* hw = hs + warp*16*S;
    float* out = (H == 64) ? g_x1 : g_x2;
    const float* Wh = (H == 64) ? g_w1b_h : g_w2b_h;
    const float* Wl = (H == 64) ? g_w1b_l : g_w2b_l;

    int jv = 0;
    if (lane < 16) jv = g_idx[(size_t)node*KNB + lane];

    if (H == 128){
        float4 a4 = *(const float4*)(g_A + (size_t)node*128 + lane*4);
        #pragma unroll 4
        for (int m = 0; m < 16; m++){
            int j = b*NN + __shfl_sync(0xffffffffu, jv, m);
            float4 c4 = *(const float4*)(g_C + (size_t)j*128 + lane*4);
            float4 h;
            h.x = leaky(a4.x + c4.x); h.y = leaky(a4.y + c4.y);
            h.z = leaky(a4.z + c4.z); h.w = leaky(a4.w + c4.w);
            *(float4*)&hw[m*S + lane*4] = h;
        }
    } else {
        float2 a2 = *(const float2*)(g_A + (size_t)node*64 + lane*2);
        #pragma unroll 4
        for (int m = 0; m < 16; m++){
            int j = b*NN + __shfl_sync(0xffffffffu, jv, m);
            float2 c2 = *(const float2*)(g_C + (size_t)j*64 + lane*2);
            float2 h;
            h.x = leaky(a2.x + c2.x); h.y = leaky(a2.y + c2.y);
            *(float2*)&hw[m*S + lane*2] = h;
        }
    }
    __syncwarp();

    float acc[8][4];
    #pragma unroll
    for (int nt = 0; nt < 8; nt++)
        #pragma unroll
        for (int i = 0; i < 4; i++) acc[nt][i] = 0.f;

    int r = lane >> 2, q = lane & 3;
    for (int kb = 0; kb < H; kb += 16){
        __syncthreads();
        for (int i = t; i < 1024; i += 128){
            int rr = i >> 6, c = i & 63;
            wsh[rr*72 + c] = Wh[(kb + rr)*64 + c];
            wsl[rr*72 + c] = Wl[(kb + rr)*64 + c];
        }
        __syncthreads();
        #pragma unroll
        for (int ks = 0; ks < 16; ks += 8){
            int k0 = kb + ks;
            unsigned ah[4], al[4];
            splt(hw[r*S + k0 + q],           ah[0], al[0]);
            splt(hw[(r+8)*S + k0 + q],       ah[1], al[1]);
            splt(hw[r*S + k0 + q + 4],       ah[2], al[2]);
            splt(hw[(r+8)*S + k0 + q + 4],   ah[3], al[3]);
            #pragma unroll
            for (int nt = 0; nt < 8; nt++){
                int bo = (ks + q)*72 + nt*8 + r;
                unsigned bh[2] = {__float_as_uint(wsh[bo]), __float_as_uint(wsh[bo + 288])};
                unsigned bl[2] = {__float_as_uint(wsl[bo]), __float_as_uint(wsl[bo + 288])};
                mma8(acc[nt], ah, bh);
                mma8(acc[nt], ah, bl);
                mma8(acc[nt], al, bh);
            }
        }
    }

    #pragma unroll
    for (int nt = 0; nt < 8; nt++){
        float m0 = fmaxf(acc[nt][0], acc[nt][2]);
        float m1 = fmaxf(acc[nt][1], acc[nt][3]);
        #pragma unroll
        for (int off = 4; off < 32; off <<= 1){
            m0 = fmaxf(m0, __shfl_xor_sync(0xffffffffu, m0, off));
            m1 = fmaxf(m1, __shfl_xor_sync(0xffffffffu, m1, off));
        }
        if (lane < 4){
            int c = nt*8 + lane*2;
            out[(size_t)node*64 + c]     = leaky(m0 + __ldg(bias + c));
            out[(size_t)node*64 + c + 1] = leaky(m1 + __ldg(bias + c + 1));
        }
    }
}

// ---------------- 4a) lin1: [BN x 136] @ [136 x 512] + leaky -> g_d2 ---------
__global__ void k_lin1(const float* __restrict__ bl1){
    __shared__ float CS[64*140];
    int t = threadIdx.x, lane = t & 31, w = t >> 5;
    int base = blockIdx.x*64;
    for (int i = t; i < 64*136; i += 256){
        int m = i / 136, d = i - m*136;
        int node = base + m;
        float v = 0.f;
        if (d < 5)        v = g_xx[node*5 + d];
        else if (d < 69)  v = g_x1[(size_t)node*64 + d - 5];
        else if (d < 133) v = g_x2[(size_t)node*64 + d - 69];
        CS[m*140 + d] = v;
    }
    __syncthreads();

    int r = lane >> 2, q = lane & 3;
    int n0 = w*64;
    for (int np = 0; np < 2; np++){
        float acc[4][4][4];
        #pragma unroll
        for (int mt = 0; mt < 4; mt++)
            #pragma unroll
            for (int nt = 0; nt < 4; nt++)
                #pragma unroll
                for (int i = 0; i < 4; i++) acc[mt][nt][i] = 0.f;

        for (int k0 = 0; k0 < 136; k0 += 8){
            unsigned ah[4][4], al[4][4];
            #pragma unroll
            for (int mt = 0; mt < 4; mt++){
                int rb = mt*16;
                splt(CS[(rb+r)*140 + k0 + q],         ah[mt][0], al[mt][0]);
                splt(CS[(rb+r+8)*140 + k0 + q],       ah[mt][1], al[mt][1]);
                splt(CS[(rb+r)*140 + k0 + q + 4],     ah[mt][2], al[mt][2]);
                splt(CS[(rb+r+8)*140 + k0 + q + 4],   ah[mt][3], al[mt][3]);
            }
            #pragma unroll
            for (int nt = 0; nt < 4; nt++){
                int col = n0 + (np*4 + nt)*8 + r;
                int o = (k0 + q)*512 + col;
                unsigned bh[2] = {__float_as_uint(__ldg(g_wl1_h + o)),
                                  __float_as_uint(__ldg(g_wl1_h + o + 2048))};
                unsigned bl[2] = {__float_as_uint(__ldg(g_wl1_l + o)),
                                  __float_as_uint(__ldg(g_wl1_l + o + 2048))};
                #pragma unroll
                for (int mt = 0; mt < 4; mt++){
                    mma8(acc[mt][nt], ah[mt], bh);
                    mma8(acc[mt][nt], ah[mt], bl);
                    mma8(acc[mt][nt], al[mt], bh);
                }
            }
        }
        #pragma unroll
        for (int mt = 0; mt < 4; mt++){
            #pragma unroll
            for (int nt = 0; nt < 4; nt++){
                int node = base + mt*16 + r;
                int col = n0 + (np*4 + nt)*8 + q*2;
                float b0 = __ldg(bl1 + col), b1 = __ldg(bl1 + col + 1);
                float2 u0, u1;
                u0.x = leaky(acc[mt][nt][0] + b0); u0.y = leaky(acc[mt][nt][1] + b1);
                u1.x = leaky(acc[mt][nt][2] + b0); u1.y = leaky(acc[mt][nt][3] + b1);
                *(float2*)(g_d2 + (size_t)node*512 + col)     = u0;
                *(float2*)(g_d2 + (size_t)(node+8)*512 + col) = u1;
            }
        }
    }
}

// ---------------- 4b) lin2: [BN x 512] @ [512 x 256] + max-pool --------------
__global__ void k_lin2(const float* __restrict__ bl2){
    __shared__ float As[64*68];
    int t = threadIdx.x, lane = t & 31, w = t >> 5;
    int base = blockIdx.x*64;
    int g = base / NN;
    int r = lane >> 2, q = lane & 3;
    int n0 = w*32;

    float acc[4][4][4];
    #pragma unroll
    for (int mt = 0; mt < 4; mt++)
        #pragma unroll
        for (int nt = 0; nt < 4; nt++)
            #pragma unroll
            for (int i = 0; i < 4; i++) acc[mt][nt][i] = 0.f;

    for (int kc = 0; kc < 512; kc += 64){
        __syncthreads();
        for (int i = t; i < 1024; i += 256){
            int m = i >> 4, kq = (i & 15)*4;
            float4 v = *(const float4*)(g_d2 + (size_t)(base + m)*512 + kc + kq);
            *(float4*)&As[m*68 + kq] = v;
        }
        __syncthreads();
        #pragma unroll
        for (int ks = 0; ks < 64; ks += 8){
            unsigned ah[4][4], al[4][4];
            #pragma unroll
            for (int mt = 0; mt < 4; mt++){
                int rb = mt*16;
                splt(As[(rb+r)*68 + ks + q],         ah[mt][0], al[mt][0]);
                splt(As[(rb+r+8)*68 + ks + q],       ah[mt][1], al[mt][1]);
                splt(As[(rb+r)*68 + ks + q + 4],     ah[mt][2], al[mt][2]);
                splt(As[(rb+r+8)*68 + ks + q + 4],   ah[mt][3], al[mt][3]);
            }
            #pragma unroll
            for (int nt = 0; nt < 4; nt++){
                int col = n0 + nt*8 + r;
                int o = (kc + ks + q)*256 + col;
                unsigned bh[2] = {__float_as_uint(__ldg(g_wl2_h + o)),
                                  __float_as_uint(__ldg(g_wl2_h + o + 1024))};
                unsigned bl[2] = {__float_as_uint(__ldg(g_wl2_l + o)),
                                  __float_as_uint(__ldg(g_wl2_l + o + 1024))};
                #pragma unroll
                for (int mt = 0; mt < 4; mt++){
                    mma8(acc[mt][nt], ah[mt], bh);
                    mma8(acc[mt][nt], ah[mt], bl);
                    mma8(acc[mt][nt], al[mt], bh);
                }
            }
        }
    }

    #pragma unroll
    for (int nt = 0; nt < 4; nt++){
        float m0 = -3.4e38f, m1 = -3.4e38f;
        #pragma unroll
        for (int mt = 0; mt < 4; mt++){
            m0 = fmaxf(m0, fmaxf(acc[mt][nt][0], acc[mt][nt][2]));
            m1 = fmaxf(m1, fmaxf(acc[mt][nt][1], acc[mt][nt][3]));
        }
        #pragma unroll
        for (int off = 4; off < 32; off <<= 1){
            m0 = fmaxf(m0, __shfl_xor_sync(0xffffffffu, m0, off));
            m1 = fmaxf(m1, __shfl_xor_sync(0xffffffffu, m1, off));
        }
        if (lane < 4){
            int col = n0 + nt*8 + lane*2;
            atomicMaxFloat(&g_pool[g*256 + col],     m0 + __ldg(bl2 + col));
            atomicMaxFloat(&g_pool[g*256 + col + 1], m1 + __ldg(bl2 + col + 1));
        }
    }
}

// ---------------- 5) head: leaky -> 256x128 -> leaky -> 128x3 ----------------
__global__ void k_head(const float* __restrict__ wm1, const float* __restrict__ bm1,
                       const float* __restrict__ wm2, const float* __restrict__ bm2,
                       float* __restrict__ out){
    __shared__ float gs[256];
    __shared__ float ms[128];
    int b = blockIdx.x, t = threadIdx.x;
    for (int c = t; c < 256; c += 128) gs[c] = leaky(g_pool[b*256 + c]);
    __syncthreads();
    float acc = bm1[t];
    #pragma unroll 8
    for (int d = 0; d < 256; d++) acc += gs[d]*wm1[d*128 + t];
    ms[t] = leaky(acc);
    __syncthreads();
    if (t < 3){
        float o = bm2[t];
        #pragma unroll 8
        for (int d = 0; d < 128; d++) o += ms[d]*wm2[d*3 + t];
        out[b*3 + t] = o;
    }
}

// -----------------------------------------------------------------------------
extern "C" void kernel_launch(void* const* d_in, const int* in_sizes, int n_in,
                              void* d_out, int out_size){
    const float* x   = (const float*)d_in[0];
    const float* pos = (const float*)d_in[1];
    const float* tq  = (const float*)d_in[2];
    const float* w1a = (const float*)d_in[4];
    const float* b1a = (const float*)d_in[5];
    const float* w1b = (const float*)d_in[6];
    const float* b1b = (const float*)d_in[7];
    const float* w2a = (const float*)d_in[8];
    const float* b2a = (const float*)d_in[9];
    const float* w2b = (const float*)d_in[10];
    const float* b2b = (const float*)d_in[11];
    const float* wl1 = (const float*)d_in[12];
    const float* bl1 = (const float*)d_in[13];
    const float* wl2 = (const float*)d_in[14];
    const float* bl2 = (const float*)d_in[15];
    const float* wm1 = (const float*)d_in[16];
    const float* bm1 = (const float*)d_in[17];
    const float* wm2 = (const float*)d_in[18];
    const float* bm2 = (const float*)d_in[19];
    float* out = (float*)d_out;

    k_prep<<<832, 256>>>(w1b, w2b, wl1, wl2);
    k_build<<<BN/256, 256>>>(x, pos, tq);
    k_initpool<<<(BATCH*256)/256, 256>>>();

    // conv1
    k_knn5<<<BATCH*(NN/8), 256>>>();
    k_convA1<<<(BN*64)/256, 256>>>(w1a, b1a);
    k_edge2t<64><<<BN/4, 128>>>(b1b);

    // conv2
    k_sq<<<BN/8, 256>>>();
    {
        dim3 grid(4, 4, BATCH);
        k_d2t<<<grid, 256>>>();
    }
    k_select<<<BN/8, 256>>>();
    k_convA2<<<BN/16, 256>>>(w2a, b2a);
    k_edge2t<128><<<BN/4, 128>>>(b2b);

    // lin1 -> g_d2 (HS), lin2 + fused pool, head
    k_lin1<<<BN/64, 256>>>(bl1);
    k_lin2<<<BN/64, 256>>>(bl2);
    k_head<<<BATCH, 128>>>(wm1, bm1, wm2, bm2, out);
}

// round 7
// speedup vs baseline: 1.4263x; 1.1092x over previous
#include <cuda_runtime.h>
#include <cuda_bf16.h>
#include <cstdint>

#define BATCH 128
#define NN    512
#define KNB   16
#define BN    (BATCH*NN)
#define NEGS  0.01f

// ---------------- scratch (device globals; no allocation allowed) -------------
__device__ float g_xx[BN*5];
__device__ float g_x1[BN*64];
__device__ float g_x2[BN*64];
__device__ int   g_idx[BN*KNB];
__device__ float g_A[(size_t)BN*128];
__device__ float g_C[(size_t)BN*128];
__device__ float g_pool[BATCH*256];
__device__ float g_sq[BN];
__device__ float g_sq5[BN];
__device__ float g_d2[(size_t)BN*NN];   // d2 matrix, later reused as HS buffer

// fragment-packed split-TF32 weights: per (kb2, ncb, lane) -> (b0h,b0l,b1h,b1l)
__device__ float4 g_w1bp[8*8*32];       // 64x64
__device__ float4 g_w2bp[16*8*32];      // 128x64
__device__ float4 g_wl1p[17*64*32];     // 136x512 (rows >=133 zero)
__device__ float4 g_wl2p[64*32*32];     // 512x256

__device__ __forceinline__ float leaky(float v){ return v > 0.f ? v : NEGS*v; }

__device__ __forceinline__ void atomicMaxFloat(float* addr, float value){
    if (value >= 0.f) atomicMax((int*)addr, __float_as_int(value));
    else              atomicMin((unsigned int*)addr, __float_as_uint(value));
}

__device__ __forceinline__ unsigned f2tf(float x){
    unsigned u; asm("cvt.rna.tf32.f32 %0, %1;" : "=r"(u) : "f"(x)); return u;
}
__device__ __forceinline__ void splt(float x, unsigned &h, unsigned &l){
    h = f2tf(x);
    l = f2tf(x - __uint_as_float(h));
}
__device__ __forceinline__ void mma8(float* c, const unsigned* a, const unsigned* b){
    asm("mma.sync.aligned.m16n8k8.row.col.f32.tf32.tf32.f32 "
        "{%0,%1,%2,%3}, {%4,%5,%6,%7}, {%8,%9}, {%0,%1,%2,%3};"
        : "+f"(c[0]), "+f"(c[1]), "+f"(c[2]), "+f"(c[3])
        : "r"(a[0]), "r"(a[1]), "r"(a[2]), "r"(a[3]), "r"(b[0]), "r"(b[1]));
}

// sortable-u32 transform: ascending uint order == ascending float order
__device__ __forceinline__ unsigned fsort(float f){
    unsigned b = __float_as_uint(f);
    return b ^ (((int)b >> 31) | 0x80000000u);
}

// warp-cooperative exact top-16-of-512 with lower-index tiebreak.
template<bool LANEMAJOR>
__device__ __forceinline__ void sel16(const float* v, int lane, int* out){
    const unsigned long long INF = ~0ull;
    unsigned long long s0 = INF, s1 = INF, s2 = INF, s3 = INF;
    #pragma unroll
    for (int u = 0; u < 16; u++){
        int j = LANEMAJOR ? (lane*16 + u) : (u*32 + lane);
        unsigned long long k = ((unsigned long long)fsort(v[u]) << 32) | (unsigned)j;
        if (k < s3){
            s3 = k;
            if (s3 < s2){ unsigned long long t = s2; s2 = s3; s3 = t; }
            if (s2 < s1){ unsigned long long t = s1; s1 = s2; s2 = t; }
            if (s1 < s0){ unsigned long long t = s0; s0 = s1; s1 = t; }
        }
    }
    unsigned mask = 0;
    int mine = 0;
    #pragma unroll 1
    for (int r = 0; r < KNB; r++){
        unsigned long long m = s0;
        #pragma unroll
        for (int off = 16; off; off >>= 1){
            unsigned long long o = __shfl_xor_sync(0xffffffffu, m, off);
            if (o < m) m = o;
        }
        if (lane == r) mine = (int)(unsigned)(m & 0xffffffffu);
        if (s0 == m){
            int j = (int)(unsigned)(m & 0xffffffffu);
            int u = LANEMAJOR ? (j & 15) : (j >> 5);
            mask |= 1u << u;
            s0 = s1; s1 = s2; s2 = s3; s3 = INF;
            if (s0 == INF && mask != 0xffffu){
                #pragma unroll
                for (int u2 = 0; u2 < 16; u2++){
                    if (!((mask >> u2) & 1u)){
                        int j2 = LANEMAJOR ? (lane*16 + u2) : (u2*32 + lane);
                        unsigned long long k = ((unsigned long long)fsort(v[u2]) << 32) | (unsigned)j2;
                        if (k < s3){
                            s3 = k;
                            if (s3 < s2){ unsigned long long t = s2; s2 = s3; s3 = t; }
                            if (s2 < s1){ unsigned long long t = s1; s1 = s2; s2 = t; }
                            if (s1 < s0){ unsigned long long t = s0; s0 = s1; s1 = t; }
                        }
                    }
                }
            }
        }
    }
    if (lane < KNB) out[lane] = mine;
}

// ---------------- prep: pool init + pack weights into fragment order ---------
__global__ void k_prep(const float* __restrict__ w1b, const float* __restrict__ w2b,
                       const float* __restrict__ wl1, const float* __restrict__ wl2){
    int i = blockIdx.x*256 + threadIdx.x;
    if (i < BATCH*256) g_pool[i] = __int_as_float(0xff800000); // -inf
    const float* W; float4* dst; int ncb, ncols, nrows, rel;
    if (i < 2048)        { W = w1b; dst = g_w1bp; ncb = 8;  ncols = 64;  nrows = 64;  rel = i; }
    else if (i < 6144)   { W = w2b; dst = g_w2bp; ncb = 8;  ncols = 64;  nrows = 128; rel = i - 2048; }
    else if (i < 40960)  { W = wl1; dst = g_wl1p; ncb = 64; ncols = 512; nrows = 133; rel = i - 6144; }
    else if (i < 106496) { W = wl2; dst = g_wl2p; ncb = 32; ncols = 256; nrows = 512; rel = i - 40960; }
    else return;
    int lane = rel & 31, tmp = rel >> 5;
    int cb = tmp % ncb, kb2 = tmp / ncb;
    int r = lane >> 2, q = lane & 3;
    int row0 = kb2*8 + q, row1 = row0 + 4, col = cb*8 + r;
    float v0 = (row0 < nrows) ? W[row0*ncols + col] : 0.f;
    float v1 = (row1 < nrows) ? W[row1*ncols + col] : 0.f;
    unsigned h0, l0, h1, l1;
    splt(v0, h0, l0); splt(v1, h1, l1);
    dst[rel] = make_float4(__uint_as_float(h0), __uint_as_float(l0),
                           __uint_as_float(h1), __uint_as_float(l1));
}

// ---------------- 0) build xx = [tq, x, pos] + 5d norms ----------------------
__global__ void k_build(const float* __restrict__ x, const float* __restrict__ pos,
                        const float* __restrict__ tq){
    int i = blockIdx.x*blockDim.x + threadIdx.x;
    if (i < BN){
        float tv = tq[i], xv = x[i];
        float p0 = pos[i*3+0], p1 = pos[i*3+1], p2 = pos[i*3+2];
        g_xx[i*5+0] = tv;
        g_xx[i*5+1] = xv;
        g_xx[i*5+2] = p0;
        g_xx[i*5+3] = p1;
        g_xx[i*5+4] = p2;
        g_sq5[i] = tv*tv + xv*xv + p0*p0 + p1*p1 + p2*p2;
    }
}

// ---------------- 1a) kNN d=5: reg query, padded tile, cached-top4 select ----
__global__ void k_knn5(){
    __shared__ float tile[128*8];    // c0..4 = feat, c5 = sq, c6..7 pad
    int b  = blockIdx.x >> 6;
    int q0 = (blockIdx.x & 63) * 8;
    int warp = threadIdx.x >> 5, lane = threadIdx.x & 31;
    int qi = q0 + warp;
    int node = b*NN + qi;
    const float* Fb = g_xx + (size_t)b*NN*5;

    float f0, f1, f2, f3, f4;
    { const float* fq = Fb + qi*5; f0=fq[0]; f1=fq[1]; f2=fq[2]; f3=fq[3]; f4=fq[4]; }
    float sqi = g_sq5[node];

    float d2loc[16];
    for (int t4 = 0; t4 < 4; t4++){
        __syncthreads();
        for (int idx = threadIdx.x; idx < 1024; idx += 256){
            int rrow = idx >> 3, c = idx & 7;
            int grow = t4*128 + rrow;
            float v = 0.f;
            if (c < 5)       v = Fb[grow*5 + c];
            else if (c == 5) v = g_sq5[b*NN + grow];
            tile[idx] = v;
        }
        __syncthreads();
        #pragma unroll
        for (int u = 0; u < 4; u++){
            int jj = u*32 + lane;
            const float* tr = &tile[jj*8];
            float4 p  = *(const float4*)tr;
            float2 p2 = *(const float2*)(tr + 4);
            float dot = f0*p.x + f1*p.y + f2*p.z + f3*p.w + f4*p2.x;
            d2loc[t4*4 + u] = sqi + p2.y - 2.f*dot;
        }
    }
    sel16<false>(d2loc, lane, g_idx + (size_t)node*KNB);
}

// ---------------- 1b) kNN d=64: row norms ------------------------------------
__global__ void k_sq(){
    int warp = threadIdx.x >> 5, lane = threadIdx.x & 31;
    int row = blockIdx.x*8 + warp;
    float2 v = ((const float2*)(g_x1 + (size_t)row*64))[lane];
    float s = v.x*v.x + v.y*v.y;
    #pragma unroll
    for (int off = 16; off > 0; off >>= 1) s += __shfl_xor_sync(0xffffffffu, s, off);
    if (lane == 0) g_sq[row] = s;
}

// ---------------- 1c) kNN d=64: pairwise d2 via split-TF32 mma ---------------
__global__ void k_d2t(){
    __shared__ float As[128*36];
    __shared__ float Bs[128*36];
    int b  = blockIdx.z;
    int i0 = blockIdx.y*128, j0 = blockIdx.x*128;
    const float* Fb = g_x1 + (size_t)b*NN*64;
    int t = threadIdx.x, lane = t & 31, w = t >> 5;
    int wx = w & 1, wy = w >> 1;
    int r = lane >> 2, q = lane & 3;

    float acc[2][8][4];
    #pragma unroll
    for (int mt = 0; mt < 2; mt++)
        #pragma unroll
        for (int nt = 0; nt < 8; nt++)
            #pragma unroll
            for (int i = 0; i < 4; i++) acc[mt][nt][i] = 0.f;

    for (int kc = 0; kc < 64; kc += 32){
        __syncthreads();
        for (int i = t; i < 128*8; i += 256){
            int m = i >> 3, kq = (i & 7)*4;
            *(float4*)&As[m*36 + kq] = *(const float4*)(Fb + (i0+m)*64 + kc + kq);
            *(float4*)&Bs[m*36 + kq] = *(const float4*)(Fb + (j0+m)*64 + kc + kq);
        }
        __syncthreads();
        #pragma unroll
        for (int k0 = 0; k0 < 32; k0 += 8){
            unsigned ah[2][4], al[2][4];
            #pragma unroll
            for (int mt = 0; mt < 2; mt++){
                int row = wy*32 + mt*16;
                splt(As[(row+r)*36 + k0 + q],       ah[mt][0], al[mt][0]);
                splt(As[(row+r+8)*36 + k0 + q],     ah[mt][1], al[mt][1]);
                splt(As[(row+r)*36 + k0 + q + 4],   ah[mt][2], al[mt][2]);
                splt(As[(row+r+8)*36 + k0 + q + 4], ah[mt][3], al[mt][3]);
            }
            #pragma unroll
            for (int nt = 0; nt < 8; nt++){
                int col = wx*64 + nt*8;
                unsigned bh[2], bl[2];
                splt(Bs[(col+r)*36 + k0 + q],     bh[0], bl[0]);
                splt(Bs[(col+r)*36 + k0 + q + 4], bh[1], bl[1]);
                #pragma unroll
                for (int mt = 0; mt < 2; mt++){
                    mma8(acc[mt][nt], ah[mt], bh);
                    mma8(acc[mt][nt], ah[mt], bl);
                    mma8(acc[mt][nt], al[mt], bh);
                }
            }
        }
    }

    #pragma unroll
    for (int mt = 0; mt < 2; mt++){
        int rowb = i0 + wy*32 + mt*16;
        float si0 = g_sq[b*NN + rowb + r];
        float si1 = g_sq[b*NN + rowb + r + 8];
        #pragma unroll
        for (int nt = 0; nt < 8; nt++){
            int colb = j0 + wx*64 + nt*8 + 2*q;
            float sj0 = g_sq[b*NN + colb], sj1 = g_sq[b*NN + colb + 1];
            float2 v0, v1;
            v0.x = si0 + sj0 - 2.f*acc[mt][nt][0];
            v0.y = si0 + sj1 - 2.f*acc[mt][nt][1];
            v1.x = si1 + sj0 - 2.f*acc[mt][nt][2];
            v1.y = si1 + sj1 - 2.f*acc[mt][nt][3];
            *(float2*)(g_d2 + (size_t)(b*NN + rowb + r)*NN + colb)     = v0;
            *(float2*)(g_d2 + (size_t)(b*NN + rowb + r + 8)*NN + colb) = v1;
        }
    }
}

// ---------------- 1d) kNN d=64: cached-top4 select ---------------------------
__global__ void k_select(){
    int warp = threadIdx.x >> 5, lane = threadIdx.x & 31;
    int node = blockIdx.x*8 + warp;
    const float* row = g_d2 + (size_t)node*NN;
    float v[16];
    #pragma unroll
    for (int u4 = 0; u4 < 4; u4++){
        float4 x = *(const float4*)(row + lane*16 + u4*4);
        v[u4*4+0] = x.x; v[u4*4+1] = x.y; v[u4*4+2] = x.z; v[u4*4+3] = x.w;
    }
    sel16<true>(v, lane, g_idx + (size_t)node*KNB);
}

// ---------------- 2a) conv1 layer-1 factorization (d=5, H=64) ----------------
__global__ void k_convA1(const float* __restrict__ W, const float* __restrict__ bias){
    int t = blockIdx.x*blockDim.x + threadIdx.x;
    if (t >= BN*64) return;
    int i = t >> 6, c = t & 63;
    const float* f = g_xx + (size_t)i*5;
    float a = bias[c], cc = 0.f;
    #pragma unroll
    for (int d = 0; d < 5; d++){
        float v  = f[d];
        float wt = W[d*64 + c];
        float wb = W[(5 + d)*64 + c];
        a  += v*(wt - wb);
        cc += v*wb;
    }
    g_A[(size_t)i*64 + c] = a;
    g_C[(size_t)i*64 + c] = cc;
}

// ---------------- 2b) conv2 layer-1 (d=64, H=128) ----------------------------
__global__ void k_convA2(const float* __restrict__ W, const float* __restrict__ bias){
    __shared__ float Wd[32*128];
    __shared__ float Wb[32*128];
    __shared__ float Fs[16*64];
    int t = threadIdx.x;
    int base = blockIdx.x*16;

    for (int idx = t; idx < 1024; idx += 256)
        Fs[idx] = g_x1[(size_t)base*64 + idx];

    int m  = t >> 4;
    int cg = (t & 15)*8;
    float a[8], cc[8];
    float4 bb0 = *(const float4*)(bias + cg);
    float4 bb1 = *(const float4*)(bias + cg + 4);
    a[0]=bb0.x; a[1]=bb0.y; a[2]=bb0.z; a[3]=bb0.w;
    a[4]=bb1.x; a[5]=bb1.y; a[6]=bb1.z; a[7]=bb1.w;
    #pragma unroll
    for (int q = 0; q < 8; q++) cc[q] = 0.f;

    for (int db = 0; db < 64; db += 32){
        __syncthreads();
        for (int idx = t; idx < 4096; idx += 256){
            int d = idx >> 7, c = idx & 127;
            float wt = W[(db + d)*128 + c];
            float wb = W[(64 + db + d)*128 + c];
            Wd[idx] = wt - wb;
            Wb[idx] = wb;
        }
        __syncthreads();
        #pragma unroll 4
        for (int d = 0; d < 32; d++){
            float v = Fs[m*64 + db + d];
            float4 w0 = *(const float4*)&Wd[d*128 + cg];
            float4 w1 = *(const float4*)&Wd[d*128 + cg + 4];
            float4 u0 = *(const float4*)&Wb[d*128 + cg];
            float4 u1 = *(const float4*)&Wb[d*128 + cg + 4];
            a[0] += v*w0.x; a[1] += v*w0.y; a[2] += v*w0.z; a[3] += v*w0.w;
            a[4] += v*w1.x; a[5] += v*w1.y; a[6] += v*w1.z; a[7] += v*w1.w;
            cc[0] += v*u0.x; cc[1] += v*u0.y; cc[2] += v*u0.z; cc[3] += v*u0.w;
            cc[4] += v*u1.x; cc[5] += v*u1.y; cc[6] += v*u1.z; cc[7] += v*u1.w;
        }
    }
    int node = base + m;
    float4* pa = (float4*)(g_A + (size_t)node*128 + cg);
    float4* pc = (float4*)(g_C + (size_t)node*128 + cg);
    pa[0] = make_float4(a[0],a[1],a[2],a[3]);
    pa[1] = make_float4(a[4],a[5],a[6],a[7]);
    pc[0] = make_float4(cc[0],cc[1],cc[2],cc[3]);
    pc[1] = make_float4(cc[4],cc[5],cc[6],cc[7]);
}

// ---------------- 3) edge MLP layer-2 + max over K — packed-B tensor cores ---
template<int H>
__global__ void k_edge2t(const float* __restrict__ bias){
    const int S = (H == 128) ? 132 : 68;
    __shared__ float hs[4*16*S];
    int t = threadIdx.x, warp = t >> 5, lane = t & 31;
    int node = blockIdx.x*4 + warp;
    int b = node / NN;
    float* hw = hs + warp*16*S;
    float* out = (H == 64) ? g_x1 : g_x2;
    const float4* wp = (H == 64) ? g_w1bp : g_w2bp;

    int jv = 0;
    if (lane < 16) jv = g_idx[(size_t)node*KNB + lane];

    if (H == 128){
        float4 a4 = *(const float4*)(g_A + (size_t)node*128 + lane*4);
        #pragma unroll 4
        for (int m = 0; m < 16; m++){
            int j = b*NN + __shfl_sync(0xffffffffu, jv, m);
            float4 c4 = *(const float4*)(g_C + (size_t)j*128 + lane*4);
            float4 h;
            h.x = leaky(a4.x + c4.x); h.y = leaky(a4.y + c4.y);
            h.z = leaky(a4.z + c4.z); h.w = leaky(a4.w + c4.w);
            *(float4*)&hw[m*S + lane*4] = h;
        }
    } else {
        float2 a2 = *(const float2*)(g_A + (size_t)node*64 + lane*2);
        #pragma unroll 4
        for (int m = 0; m < 16; m++){
            int j = b*NN + __shfl_sync(0xffffffffu, jv, m);
            float2 c2 = *(const float2*)(g_C + (size_t)j*64 + lane*2);
            float2 h;
            h.x = leaky(a2.x + c2.x); h.y = leaky(a2.y + c2.y);
            *(float2*)&hw[m*S + lane*2] = h;
        }
    }
    __syncwarp();

    float acc[8][4];
    #pragma unroll
    for (int nt = 0; nt < 8; nt++)
        #pragma unroll
        for (int i = 0; i < 4; i++) acc[nt][i] = 0.f;

    int r = lane >> 2, q = lane & 3;
    #pragma unroll 4
    for (int kb2 = 0; kb2 < H/8; kb2++){
        int k0 = kb2*8;
        unsigned ah[4], al[4];
        splt(hw[r*S + k0 + q],           ah[0], al[0]);
        splt(hw[(r+8)*S + k0 + q],       ah[1], al[1]);
        splt(hw[r*S + k0 + q + 4],       ah[2], al[2]);
        splt(hw[(r+8)*S + k0 + q + 4],   ah[3], al[3]);
        #pragma unroll
        for (int nt = 0; nt < 8; nt++){
            float4 wv = __ldg(&wp[(kb2*8 + nt)*32 + lane]);
            unsigned bh[2] = {__float_as_uint(wv.x), __float_as_uint(wv.z)};
            unsigned bl[2] = {__float_as_uint(wv.y), __float_as_uint(wv.w)};
            mma8(acc[nt], ah, bh);
            mma8(acc[nt], ah, bl);
            mma8(acc[nt], al, bh);
        }
    }

    #pragma unroll
    for (int nt = 0; nt < 8; nt++){
        float m0 = fmaxf(acc[nt][0], acc[nt][2]);
        float m1 = fmaxf(acc[nt][1], acc[nt][3]);
        #pragma unroll
        for (int off = 4; off < 32; off <<= 1){
            m0 = fmaxf(m0, __shfl_xor_sync(0xffffffffu, m0, off));
            m1 = fmaxf(m1, __shfl_xor_sync(0xffffffffu, m1, off));
        }
        if (lane < 4){
            int c = nt*8 + lane*2;
            out[(size_t)node*64 + c]     = leaky(m0 + __ldg(bias + c));
            out[(size_t)node*64 + c + 1] = leaky(m1 + __ldg(bias + c + 1));
        }
    }
}

// ---------------- 4a) lin1: [BN x 136] @ [136 x 512] + leaky -> g_d2 ---------
__global__ void k_lin1(const float* __restrict__ bl1){
    __shared__ float CS[64*140];
    int t = threadIdx.x, lane = t & 31, w = t >> 5;
    int base = blockIdx.x*64;
    for (int i = t; i < 64*136; i += 256){
        int m = i / 136, d = i - m*136;
        int node = base + m;
        float v = 0.f;
        if (d < 5)        v = g_xx[node*5 + d];
        else if (d < 69)  v = g_x1[(size_t)node*64 + d - 5];
        else if (d < 133) v = g_x2[(size_t)node*64 + d - 69];
        CS[m*140 + d] = v;
    }
    __syncthreads();

    int r = lane >> 2, q = lane & 3;
    int n0 = w*64;
    for (int np = 0; np < 2; np++){
        float acc[4][4][4];
        #pragma unroll
        for (int mt = 0; mt < 4; mt++)
            #pragma unroll
            for (int nt = 0; nt < 4; nt++)
                #pragma unroll
                for (int i = 0; i < 4; i++) acc[mt][nt][i] = 0.f;

        for (int k0 = 0; k0 < 136; k0 += 8){
            unsigned ah[4][4], al[4][4];
            #pragma unroll
            for (int mt = 0; mt < 4; mt++){
                int rb = mt*16;
                splt(CS[(rb+r)*140 + k0 + q],         ah[mt][0], al[mt][0]);
                splt(CS[(rb+r+8)*140 + k0 + q],       ah[mt][1], al[mt][1]);
                splt(CS[(rb+r)*140 + k0 + q + 4],     ah[mt][2], al[mt][2]);
                splt(CS[(rb+r+8)*140 + k0 + q + 4],   ah[mt][3], al[mt][3]);
            }
            #pragma unroll
            for (int nt = 0; nt < 4; nt++){
                float4 wv = __ldg(&g_wl1p[(((unsigned)k0 >> 3)*64 + w*8 + np*4 + nt)*32 + lane]);
                unsigned bh[2] = {__float_as_uint(wv.x), __float_as_uint(wv.z)};
                unsigned bl[2] = {__float_as_uint(wv.y), __float_as_uint(wv.w)};
                #pragma unroll
                for (int mt = 0; mt < 4; mt++){
                    mma8(acc[mt][nt], ah[mt], bh);
                    mma8(acc[mt][nt], ah[mt], bl);
                    mma8(acc[mt][nt], al[mt], bh);
                }
            }
        }
        #pragma unroll
        for (int mt = 0; mt < 4; mt++){
            #pragma unroll
            for (int nt = 0; nt < 4; nt++){
                int node = base + mt*16 + r;
                int col = n0 + (np*4 + nt)*8 + q*2;
                float b0 = __ldg(bl1 + col), b1 = __ldg(bl1 + col + 1);
                float2 u0, u1;
                u0.x = leaky(acc[mt][nt][0] + b0); u0.y = leaky(acc[mt][nt][1] + b1);
                u1.x = leaky(acc[mt][nt][2] + b0); u1.y = leaky(acc[mt][nt][3] + b1);
                *(float2*)(g_d2 + (size_t)node*512 + col)     = u0;
                *(float2*)(g_d2 + (size_t)(node+8)*512 + col) = u1;
            }
        }
    }
}

// ---------------- 4b) lin2: [BN x 512] @ [512 x 256] + max-pool --------------
__global__ void k_lin2(const float* __restrict__ bl2){
    __shared__ float As[64*68];
    int t = threadIdx.x, lane = t & 31, w = t >> 5;
    int base = blockIdx.x*64;
    int g = base / NN;
    int r = lane >> 2, q = lane & 3;
    int n0 = w*32;

    float acc[4][4][4];
    #pragma unroll
    for (int mt = 0; mt < 4; mt++)
        #pragma unroll
        for (int nt = 0; nt < 4; nt++)
            #pragma unroll
            for (int i = 0; i < 4; i++) acc[mt][nt][i] = 0.f;

    for (int kc = 0; kc < 512; kc += 64){
        __syncthreads();
        for (int i = t; i < 1024; i += 256){
            int m = i >> 4, kq = (i & 15)*4;
            float4 v = *(const float4*)(g_d2 + (size_t)(base + m)*512 + kc + kq);
            *(float4*)&As[m*68 + kq] = v;
        }
        __syncthreads();
        #pragma unroll
        for (int ks = 0; ks < 64; ks += 8){
            unsigned ah[4][4], al[4][4];
            #pragma unroll
            for (int mt = 0; mt < 4; mt++){
                int rb = mt*16;
                splt(As[(rb+r)*68 + ks + q],         ah[mt][0], al[mt][0]);
                splt(As[(rb+r+8)*68 + ks + q],       ah[mt][1], al[mt][1]);
                splt(As[(rb+r)*68 + ks + q + 4],     ah[mt][2], al[mt][2]);
                splt(As[(rb+r+8)*68 + ks + q + 4],   ah[mt][3], al[mt][3]);
            }
            #pragma unroll
            for (int nt = 0; nt < 4; nt++){
                float4 wv = __ldg(&g_wl2p[((unsigned)(kc + ks) >> 3)*32*32 + (w*4 + nt)*32 + lane]);
                unsigned bh[2] = {__float_as_uint(wv.x), __float_as_uint(wv.z)};
                unsigned bl[2] = {__float_as_uint(wv.y), __float_as_uint(wv.w)};
                #pragma unroll
                for (int mt = 0; mt < 4; mt++){
                    mma8(acc[mt][nt], ah[mt], bh);
                    mma8(acc[mt][nt], ah[mt], bl);
                    mma8(acc[mt][nt], al[mt], bh);
                }
            }
        }
    }

    #pragma unroll
    for (int nt = 0; nt < 4; nt++){
        float m0 = -3.4e38f, m1 = -3.4e38f;
        #pragma unroll
        for (int mt = 0; mt < 4; mt++){
            m0 = fmaxf(m0, fmaxf(acc[mt][nt][0], acc[mt][nt][2]));
            m1 = fmaxf(m1, fmaxf(acc[mt][nt][1], acc[mt][nt][3]));
        }
        #pragma unroll
        for (int off = 4; off < 32; off <<= 1){
            m0 = fmaxf(m0, __shfl_xor_sync(0xffffffffu, m0, off));
            m1 = fmaxf(m1, __shfl_xor_sync(0xffffffffu, m1, off));
        }
        if (lane < 4){
            int col = n0 + nt*8 + lane*2;
            atomicMaxFloat(&g_pool[g*256 + col],     m0 + __ldg(bl2 + col));
            atomicMaxFloat(&g_pool[g*256 + col + 1], m1 + __ldg(bl2 + col + 1));
        }
    }
}

// ---------------- 5) head: leaky -> 256x128 -> leaky -> 128x3 ----------------
__global__ void k_head(const float* __restrict__ wm1, const float* __restrict__ bm1,
                       const float* __restrict__ wm2, const float* __restrict__ bm2,
                       float* __restrict__ out){
    __shared__ float gs[256];
    __shared__ float ms[128];
    int b = blockIdx.x, t = threadIdx.x;
    for (int c = t; c < 256; c += 128) gs[c] = leaky(g_pool[b*256 + c]);
    __syncthreads();
    float acc = bm1[t];
    #pragma unroll 8
    for (int d = 0; d < 256; d++) acc += gs[d]*wm1[d*128 + t];
    ms[t] = leaky(acc);
    __syncthreads();
    if (t < 3){
        float o = bm2[t];
        #pragma unroll 8
        for (int d = 0; d < 128; d++) o += ms[d]*wm2[d*3 + t];
        out[b*3 + t] = o;
    }
}

// -----------------------------------------------------------------------------
extern "C" void kernel_launch(void* const* d_in, const int* in_sizes, int n_in,
                              void* d_out, int out_size){
    const float* x   = (const float*)d_in[0];
    const float* pos = (const float*)d_in[1];
    const float* tq  = (const float*)d_in[2];
    const float* w1a = (const float*)d_in[4];
    const float* b1a = (const float*)d_in[5];
    const float* w1b = (const float*)d_in[6];
    const float* b1b = (const float*)d_in[7];
    const float* w2a = (const float*)d_in[8];
    const float* b2a = (const float*)d_in[9];
    const float* w2b = (const float*)d_in[10];
    const float* b2b = (const float*)d_in[11];
    const float* wl1 = (const float*)d_in[12];
    const float* bl1 = (const float*)d_in[13];
    const float* wl2 = (const float*)d_in[14];
    const float* bl2 = (const float*)d_in[15];
    const float* wm1 = (const float*)d_in[16];
    const float* bm1 = (const float*)d_in[17];
    const float* wm2 = (const float*)d_in[18];
    const float* bm2 = (const float*)d_in[19];
    float* out = (float*)d_out;

    k_prep<<<416, 256>>>(w1b, w2b, wl1, wl2);
    k_build<<<BN/256, 256>>>(x, pos, tq);

    // conv1
    k_knn5<<<BATCH*(NN/8), 256>>>();
    k_convA1<<<(BN*64)/256, 256>>>(w1a, b1a);
    k_edge2t<64><<<BN/4, 128>>>(b1b);

    // conv2
    k_sq<<<BN/8, 256>>>();
    {
        dim3 grid(4, 4, BATCH);
        k_d2t<<<grid, 256>>>();
    }
    k_select<<<BN/8, 256>>>();
    k_convA2<<<BN/16, 256>>>(w2a, b2a);
    k_edge2t<128><<<BN/4, 128>>>(b2b);

    // lin1 -> g_d2 (HS), lin2 + fused pool, head
    k_lin1<<<BN/64, 256>>>(bl1);
    k_lin2<<<BN/64, 256>>>(bl2);
    k_head<<<BATCH, 128>>>(wm1, bm1, wm2, bm2, out);
}

// round 8
// speedup vs baseline: 1.7893x; 1.2545x over previous
#include <cuda_runtime.h>
#include <cuda_bf16.h>
#include <cstdint>

#define BATCH 128
#define NN    512
#define KNB   16
#define BN    (BATCH*NN)
#define NEGS  0.01f

// ---------------- scratch (device globals; no allocation allowed) -------------
__device__ float g_xx[BN*5];
__device__ float g_x1[BN*64];
__device__ float g_x2[BN*64];
__device__ int   g_idx[BN*KNB];
__device__ float g_A[(size_t)BN*128];
__device__ float g_C[(size_t)BN*128];
__device__ float g_pool[BATCH*256];
__device__ float g_sq[BN];
__device__ float g_sq5[BN];
__device__ float g_d2[(size_t)BN*NN];   // d2 matrix, later reused as HS buffer

// tf32 fragment-packed weights (edge64 only; exact path feeding kNN2)
__device__ float4 g_w1bp[8*8*32];        // 64x64
// bf16 split fragment-packed weights: uint4 = (bh0, bh1, bl0, bl1)
__device__ uint4  g_w2bpb[8*8*32];       // 128x64
__device__ uint4  g_wl1pb[9*64*32];      // 144x512 (rows >=133 zero)
__device__ uint4  g_wl2pb[32*32*32];     // 512x256

__device__ __forceinline__ float leaky(float v){ return v > 0.f ? v : NEGS*v; }

__device__ __forceinline__ void atomicMaxFloat(float* addr, float value){
    if (value >= 0.f) atomicMax((int*)addr, __float_as_int(value));
    else              atomicMin((unsigned int*)addr, __float_as_uint(value));
}

__device__ __forceinline__ unsigned f2tf(float x){
    unsigned u; asm("cvt.rna.tf32.f32 %0, %1;" : "=r"(u) : "f"(x)); return u;
}
__device__ __forceinline__ void splt(float x, unsigned &h, unsigned &l){
    h = f2tf(x);
    l = f2tf(x - __uint_as_float(h));
}
__device__ __forceinline__ void mma8(float* c, const unsigned* a, const unsigned* b){
    asm("mma.sync.aligned.m16n8k8.row.col.f32.tf32.tf32.f32 "
        "{%0,%1,%2,%3}, {%4,%5,%6,%7}, {%8,%9}, {%0,%1,%2,%3};"
        : "+f"(c[0]), "+f"(c[1]), "+f"(c[2]), "+f"(c[3])
        : "r"(a[0]), "r"(a[1]), "r"(a[2]), "r"(a[3]), "r"(b[0]), "r"(b[1]));
}
__device__ __forceinline__ void mma16(float* c, const unsigned* a, const unsigned* b){
    asm("mma.sync.aligned.m16n8k16.row.col.f32.bf16.bf16.f32 "
        "{%0,%1,%2,%3}, {%4,%5,%6,%7}, {%8,%9}, {%0,%1,%2,%3};"
        : "+f"(c[0]), "+f"(c[1]), "+f"(c[2]), "+f"(c[3])
        : "r"(a[0]), "r"(a[1]), "r"(a[2]), "r"(a[3]), "r"(b[0]), "r"(b[1]));
}
// pack (v0 -> low bf16, v1 -> high bf16)
__device__ __forceinline__ unsigned packbf(float v0, float v1){
    unsigned d; asm("cvt.rn.bf16x2.f32 %0, %1, %2;" : "=r"(d) : "f"(v1), "f"(v0)); return d;
}
__device__ __forceinline__ float bflo(unsigned p){ return __uint_as_float(p << 16); }
__device__ __forceinline__ float bfhi(unsigned p){ return __uint_as_float(p & 0xffff0000u); }
// split pair into bf16 hi + bf16 residual
__device__ __forceinline__ void split2(float v0, float v1, unsigned &h, unsigned &l){
    h = packbf(v0, v1);
    l = packbf(v0 - bflo(h), v1 - bfhi(h));
}

// sortable-u32 transform: ascending uint order == ascending float order
__device__ __forceinline__ unsigned fsort(float f){
    unsigned b = __float_as_uint(f);
    return b ^ (((int)b >> 31) | 0x80000000u);
}

// warp-cooperative exact top-16-of-512 with lower-index tiebreak.
template<bool LANEMAJOR>
__device__ __forceinline__ void sel16(const float* v, int lane, int* out){
    const unsigned long long INF = ~0ull;
    unsigned long long s0 = INF, s1 = INF, s2 = INF, s3 = INF;
    #pragma unroll
    for (int u = 0; u < 16; u++){
        int j = LANEMAJOR ? (lane*16 + u) : (u*32 + lane);
        unsigned long long k = ((unsigned long long)fsort(v[u]) << 32) | (unsigned)j;
        if (k < s3){
            s3 = k;
            if (s3 < s2){ unsigned long long t = s2; s2 = s3; s3 = t; }
            if (s2 < s1){ unsigned long long t = s1; s1 = s2; s2 = t; }
            if (s1 < s0){ unsigned long long t = s0; s0 = s1; s1 = t; }
        }
    }
    unsigned mask = 0;
    int mine = 0;
    #pragma unroll 1
    for (int r = 0; r < KNB; r++){
        unsigned long long m = s0;
        #pragma unroll
        for (int off = 16; off; off >>= 1){
            unsigned long long o = __shfl_xor_sync(0xffffffffu, m, off);
            if (o < m) m = o;
        }
        if (lane == r) mine = (int)(unsigned)(m & 0xffffffffu);
        if (s0 == m){
            int j = (int)(unsigned)(m & 0xffffffffu);
            int u = LANEMAJOR ? (j & 15) : (j >> 5);
            mask |= 1u << u;
            s0 = s1; s1 = s2; s2 = s3; s3 = INF;
            if (s0 == INF && mask != 0xffffu){
                #pragma unroll
                for (int u2 = 0; u2 < 16; u2++){
                    if (!((mask >> u2) & 1u)){
                        int j2 = LANEMAJOR ? (lane*16 + u2) : (u2*32 + lane);
                        unsigned long long k = ((unsigned long long)fsort(v[u2]) << 32) | (unsigned)j2;
                        if (k < s3){
                            s3 = k;
                            if (s3 < s2){ unsigned long long t = s2; s2 = s3; s3 = t; }
                            if (s2 < s1){ unsigned long long t = s1; s1 = s2; s2 = t; }
                            if (s1 < s0){ unsigned long long t = s0; s0 = s1; s1 = t; }
                        }
                    }
                }
            }
        }
    }
    if (lane < KNB) out[lane] = mine;
}

// ---------------- prep: pool init + pack weights ------------------------------
__global__ void k_prep(const float* __restrict__ w1b, const float* __restrict__ w2b,
                       const float* __restrict__ wl1, const float* __restrict__ wl2){
    int i = blockIdx.x*256 + threadIdx.x;
    if (i < BATCH*256) g_pool[i] = __int_as_float(0xff800000); // -inf

    if (i < 2048){
        // tf32 pack for w1b (64x64): per (kb2, cb, lane)
        int lane = i & 31, tmp = i >> 5;
        int cb = tmp & 7, kb2 = tmp >> 3;
        int r = lane >> 2, q = lane & 3;
        int row0 = kb2*8 + q, row1 = row0 + 4, col = cb*8 + r;
        float v0 = w1b[row0*64 + col];
        float v1 = w1b[row1*64 + col];
        unsigned h0, l0, h1, l1;
        splt(v0, h0, l0); splt(v1, h1, l1);
        g_w1bp[i] = make_float4(__uint_as_float(h0), __uint_as_float(l0),
                                __uint_as_float(h1), __uint_as_float(l1));
    } else if (i < 55296){
        const float* W; uint4* dst; int ncb, ncols, nrows, rel;
        if (i < 4096)       { rel = i - 2048;  W = w2b; dst = g_w2bpb; ncb = 8;  ncols = 64;  nrows = 128; }
        else if (i < 22528) { rel = i - 4096;  W = wl1; dst = g_wl1pb; ncb = 64; ncols = 512; nrows = 133; }
        else                { rel = i - 22528; W = wl2; dst = g_wl2pb; ncb = 32; ncols = 256; nrows = 512; }
        int lane = rel & 31, tmp = rel >> 5;
        int cb = tmp % ncb, kb = tmp / ncb;
        int r = lane >> 2, q = lane & 3, col = cb*8 + r;
        int k0 = kb*16 + 2*q;
        float v00 = (k0     < nrows) ? W[(k0    )*ncols + col] : 0.f;
        float v01 = (k0 + 1 < nrows) ? W[(k0 + 1)*ncols + col] : 0.f;
        float v10 = (k0 + 8 < nrows) ? W[(k0 + 8)*ncols + col] : 0.f;
        float v11 = (k0 + 9 < nrows) ? W[(k0 + 9)*ncols + col] : 0.f;
        unsigned h0, l0, h1, l1;
        split2(v00, v01, h0, l0);
        split2(v10, v11, h1, l1);
        dst[rel] = make_uint4(h0, h1, l0, l1);
    }
}

// ---------------- 0) build xx = [tq, x, pos] + 5d norms ----------------------
__global__ void k_build(const float* __restrict__ x, const float* __restrict__ pos,
                        const float* __restrict__ tq){
    int i = blockIdx.x*blockDim.x + threadIdx.x;
    if (i < BN){
        float tv = tq[i], xv = x[i];
        float p0 = pos[i*3+0], p1 = pos[i*3+1], p2 = pos[i*3+2];
        g_xx[i*5+0] = tv;
        g_xx[i*5+1] = xv;
        g_xx[i*5+2] = p0;
        g_xx[i*5+3] = p1;
        g_xx[i*5+4] = p2;
        g_sq5[i] = tv*tv + xv*xv + p0*p0 + p1*p1 + p2*p2;
    }
}

// ---------------- 1a) kNN d=5 ------------------------------------------------
__global__ void k_knn5(){
    __shared__ float tile[128*8];    // c0..4 = feat, c5 = sq, c6..7 pad
    int b  = blockIdx.x >> 6;
    int q0 = (blockIdx.x & 63) * 8;
    int warp = threadIdx.x >> 5, lane = threadIdx.x & 31;
    int qi = q0 + warp;
    int node = b*NN + qi;
    const float* Fb = g_xx + (size_t)b*NN*5;

    float f0, f1, f2, f3, f4;
    { const float* fq = Fb + qi*5; f0=fq[0]; f1=fq[1]; f2=fq[2]; f3=fq[3]; f4=fq[4]; }
    float sqi = g_sq5[node];

    float d2loc[16];
    for (int t4 = 0; t4 < 4; t4++){
        __syncthreads();
        for (int idx = threadIdx.x; idx < 1024; idx += 256){
            int rrow = idx >> 3, c = idx & 7;
            int grow = t4*128 + rrow;
            float v = 0.f;
            if (c < 5)       v = Fb[grow*5 + c];
            else if (c == 5) v = g_sq5[b*NN + grow];
            tile[idx] = v;
        }
        __syncthreads();
        #pragma unroll
        for (int u = 0; u < 4; u++){
            int jj = u*32 + lane;
            const float* tr = &tile[jj*8];
            float4 p  = *(const float4*)tr;
            float2 p2 = *(const float2*)(tr + 4);
            float dot = f0*p.x + f1*p.y + f2*p.z + f3*p.w + f4*p2.x;
            d2loc[t4*4 + u] = sqi + p2.y - 2.f*dot;
        }
    }
    sel16<false>(d2loc, lane, g_idx + (size_t)node*KNB);
}

// ---------------- 1c) kNN d=64: pairwise d2 via split-TF32 mma ---------------
__global__ void k_d2t(){
    __shared__ float As[128*36];
    __shared__ float Bs[128*36];
    int b  = blockIdx.z;
    int i0 = blockIdx.y*128, j0 = blockIdx.x*128;
    const float* Fb = g_x1 + (size_t)b*NN*64;
    int t = threadIdx.x, lane = t & 31, w = t >> 5;
    int wx = w & 1, wy = w >> 1;
    int r = lane >> 2, q = lane & 3;

    float acc[2][8][4];
    #pragma unroll
    for (int mt = 0; mt < 2; mt++)
        #pragma unroll
        for (int nt = 0; nt < 8; nt++)
            #pragma unroll
            for (int i = 0; i < 4; i++) acc[mt][nt][i] = 0.f;

    for (int kc = 0; kc < 64; kc += 32){
        __syncthreads();
        for (int i = t; i < 128*8; i += 256){
            int m = i >> 3, kq = (i & 7)*4;
            *(float4*)&As[m*36 + kq] = *(const float4*)(Fb + (i0+m)*64 + kc + kq);
            *(float4*)&Bs[m*36 + kq] = *(const float4*)(Fb + (j0+m)*64 + kc + kq);
        }
        __syncthreads();
        #pragma unroll
        for (int k0 = 0; k0 < 32; k0 += 8){
            unsigned ah[2][4], al[2][4];
            #pragma unroll
            for (int mt = 0; mt < 2; mt++){
                int row = wy*32 + mt*16;
                splt(As[(row+r)*36 + k0 + q],       ah[mt][0], al[mt][0]);
                splt(As[(row+r+8)*36 + k0 + q],     ah[mt][1], al[mt][1]);
                splt(As[(row+r)*36 + k0 + q + 4],   ah[mt][2], al[mt][2]);
                splt(As[(row+r+8)*36 + k0 + q + 4], ah[mt][3], al[mt][3]);
            }
            #pragma unroll
            for (int nt = 0; nt < 8; nt++){
                int col = wx*64 + nt*8;
                unsigned bh[2], bl[2];
                splt(Bs[(col+r)*36 + k0 + q],     bh[0], bl[0]);
                splt(Bs[(col+r)*36 + k0 + q + 4], bh[1], bl[1]);
                #pragma unroll
                for (int mt = 0; mt < 2; mt++){
                    mma8(acc[mt][nt], ah[mt], bh);
                    mma8(acc[mt][nt], ah[mt], bl);
                    mma8(acc[mt][nt], al[mt], bh);
                }
            }
        }
    }

    #pragma unroll
    for (int mt = 0; mt < 2; mt++){
        int rowb = i0 + wy*32 + mt*16;
        float si0 = g_sq[b*NN + rowb + r];
        float si1 = g_sq[b*NN + rowb + r + 8];
        #pragma unroll
        for (int nt = 0; nt < 8; nt++){
            int colb = j0 + wx*64 + nt*8 + 2*q;
            float sj0 = g_sq[b*NN + colb], sj1 = g_sq[b*NN + colb + 1];
            float2 v0, v1;
            v0.x = si0 + sj0 - 2.f*acc[mt][nt][0];
            v0.y = si0 + sj1 - 2.f*acc[mt][nt][1];
            v1.x = si1 + sj0 - 2.f*acc[mt][nt][2];
            v1.y = si1 + sj1 - 2.f*acc[mt][nt][3];
            *(float2*)(g_d2 + (size_t)(b*NN + rowb + r)*NN + colb)     = v0;
            *(float2*)(g_d2 + (size_t)(b*NN + rowb + r + 8)*NN + colb) = v1;
        }
    }
}

// ---------------- 1d) kNN d=64: cached-top4 select ---------------------------
__global__ void k_select(){
    int warp = threadIdx.x >> 5, lane = threadIdx.x & 31;
    int node = blockIdx.x*8 + warp;
    const float* row = g_d2 + (size_t)node*NN;
    float v[16];
    #pragma unroll
    for (int u4 = 0; u4 < 4; u4++){
        float4 x = *(const float4*)(row + lane*16 + u4*4);
        v[u4*4+0] = x.x; v[u4*4+1] = x.y; v[u4*4+2] = x.z; v[u4*4+3] = x.w;
    }
    sel16<true>(v, lane, g_idx + (size_t)node*KNB);
}

// ---------------- 2a) conv1 layer-1 factorization (d=5, H=64) ----------------
__global__ void k_convA1(const float* __restrict__ W, const float* __restrict__ bias){
    int t = blockIdx.x*blockDim.x + threadIdx.x;
    if (t >= BN*64) return;
    int i = t >> 6, c = t & 63;
    const float* f = g_xx + (size_t)i*5;
    float a = bias[c], cc = 0.f;
    #pragma unroll
    for (int d = 0; d < 5; d++){
        float v  = f[d];
        float wt = W[d*64 + c];
        float wb = W[(5 + d)*64 + c];
        a  += v*(wt - wb);
        cc += v*wb;
    }
    g_A[(size_t)i*64 + c] = a;
    g_C[(size_t)i*64 + c] = cc;
}

// ---------------- 2b) conv2 layer-1 (d=64, H=128) ----------------------------
__global__ void k_convA2(const float* __restrict__ W, const float* __restrict__ bias){
    __shared__ float Wd[32*128];
    __shared__ float Wb[32*128];
    __shared__ float Fs[16*64];
    int t = threadIdx.x;
    int base = blockIdx.x*16;

    for (int idx = t; idx < 1024; idx += 256)
        Fs[idx] = g_x1[(size_t)base*64 + idx];

    int m  = t >> 4;
    int cg = (t & 15)*8;
    float a[8], cc[8];
    float4 bb0 = *(const float4*)(bias + cg);
    float4 bb1 = *(const float4*)(bias + cg + 4);
    a[0]=bb0.x; a[1]=bb0.y; a[2]=bb0.z; a[3]=bb0.w;
    a[4]=bb1.x; a[5]=bb1.y; a[6]=bb1.z; a[7]=bb1.w;
    #pragma unroll
    for (int q = 0; q < 8; q++) cc[q] = 0.f;

    for (int db = 0; db < 64; db += 32){
        __syncthreads();
        for (int idx = t; idx < 4096; idx += 256){
            int d = idx >> 7, c = idx & 127;
            float wt = W[(db + d)*128 + c];
            float wb = W[(64 + db + d)*128 + c];
            Wd[idx] = wt - wb;
            Wb[idx] = wb;
        }
        __syncthreads();
        #pragma unroll 4
        for (int d = 0; d < 32; d++){
            float v = Fs[m*64 + db + d];
            float4 w0 = *(const float4*)&Wd[d*128 + cg];
            float4 w1 = *(const float4*)&Wd[d*128 + cg + 4];
            float4 u0 = *(const float4*)&Wb[d*128 + cg];
            float4 u1 = *(const float4*)&Wb[d*128 + cg + 4];
            a[0] += v*w0.x; a[1] += v*w0.y; a[2] += v*w0.z; a[3] += v*w0.w;
            a[4] += v*w1.x; a[5] += v*w1.y; a[6] += v*w1.z; a[7] += v*w1.w;
            cc[0] += v*u0.x; cc[1] += v*u0.y; cc[2] += v*u0.z; cc[3] += v*u0.w;
            cc[4] += v*u1.x; cc[5] += v*u1.y; cc[6] += v*u1.z; cc[7] += v*u1.w;
        }
    }
    int node = base + m;
    float4* pa = (float4*)(g_A + (size_t)node*128 + cg);
    float4* pc = (float4*)(g_C + (size_t)node*128 + cg);
    pa[0] = make_float4(a[0],a[1],a[2],a[3]);
    pa[1] = make_float4(a[4],a[5],a[6],a[7]);
    pc[0] = make_float4(cc[0],cc[1],cc[2],cc[3]);
    pc[1] = make_float4(cc[4],cc[5],cc[6],cc[7]);
}

// ---------------- 3a) conv1 edge layer-2 + max + fused sq (tf32, exact) ------
__global__ void k_edge64(const float* __restrict__ bias){
    const int S = 68;
    __shared__ float hs[4*16*S];
    int t = threadIdx.x, warp = t >> 5, lane = t & 31;
    int node = blockIdx.x*4 + warp;
    int b = node / NN;
    float* hw = hs + warp*16*S;

    int jv = 0;
    if (lane < 16) jv = g_idx[(size_t)node*KNB + lane];

    float2 a2 = *(const float2*)(g_A + (size_t)node*64 + lane*2);
    #pragma unroll 4
    for (int m = 0; m < 16; m++){
        int j = b*NN + __shfl_sync(0xffffffffu, jv, m);
        float2 c2 = *(const float2*)(g_C + (size_t)j*64 + lane*2);
        float2 h;
        h.x = leaky(a2.x + c2.x); h.y = leaky(a2.y + c2.y);
        *(float2*)&hw[m*S + lane*2] = h;
    }
    __syncwarp();

    float acc[8][4];
    #pragma unroll
    for (int nt = 0; nt < 8; nt++)
        #pragma unroll
        for (int i = 0; i < 4; i++) acc[nt][i] = 0.f;

    int r = lane >> 2, q = lane & 3;
    #pragma unroll
    for (int kb2 = 0; kb2 < 8; kb2++){
        int k0 = kb2*8;
        unsigned ah[4], al[4];
        splt(hw[r*S + k0 + q],           ah[0], al[0]);
        splt(hw[(r+8)*S + k0 + q],       ah[1], al[1]);
        splt(hw[r*S + k0 + q + 4],       ah[2], al[2]);
        splt(hw[(r+8)*S + k0 + q + 4],   ah[3], al[3]);
        #pragma unroll
        for (int nt = 0; nt < 8; nt++){
            float4 wv = __ldg(&g_w1bp[(kb2*8 + nt)*32 + lane]);
            unsigned bh[2] = {__float_as_uint(wv.x), __float_as_uint(wv.z)};
            unsigned bl[2] = {__float_as_uint(wv.y), __float_as_uint(wv.w)};
            mma8(acc[nt], ah, bh);
            mma8(acc[nt], ah, bl);
            mma8(acc[nt], al, bh);
        }
    }

    float ssum = 0.f;
    #pragma unroll
    for (int nt = 0; nt < 8; nt++){
        float m0 = fmaxf(acc[nt][0], acc[nt][2]);
        float m1 = fmaxf(acc[nt][1], acc[nt][3]);
        #pragma unroll
        for (int off = 4; off < 32; off <<= 1){
            m0 = fmaxf(m0, __shfl_xor_sync(0xffffffffu, m0, off));
            m1 = fmaxf(m1, __shfl_xor_sync(0xffffffffu, m1, off));
        }
        if (lane < 4){
            int c = nt*8 + lane*2;
            float v0 = leaky(m0 + __ldg(bias + c));
            float v1 = leaky(m1 + __ldg(bias + c + 1));
            g_x1[(size_t)node*64 + c]     = v0;
            g_x1[(size_t)node*64 + c + 1] = v1;
            ssum += v0*v0 + v1*v1;
        }
    }
    // reduce squares over lanes 0..3 (others hold 0)
    ssum += __shfl_xor_sync(0xffffffffu, ssum, 1);
    ssum += __shfl_xor_sync(0xffffffffu, ssum, 2);
    if (lane == 0) g_sq[node] = ssum;
}

// ---------------- 3b) conv2 edge layer-2 + max — split-bf16 m16n8k16 ---------
__global__ void k_edge128(const float* __restrict__ bias){
    __shared__ unsigned hsh[4*16*68];
    __shared__ unsigned hsl[4*16*68];
    int t = threadIdx.x, warp = t >> 5, lane = t & 31;
    int node = blockIdx.x*4 + warp;
    int b = node / NN;
    unsigned* hh = hsh + warp*16*68;
    unsigned* hl = hsl + warp*16*68;

    int jv = 0;
    if (lane < 16) jv = g_idx[(size_t)node*KNB + lane];

    float4 a4 = *(const float4*)(g_A + (size_t)node*128 + lane*4);
    #pragma unroll 4
    for (int m = 0; m < 16; m++){
        int j = b*NN + __shfl_sync(0xffffffffu, jv, m);
        float4 c4 = *(const float4*)(g_C + (size_t)j*128 + lane*4);
        float h0 = leaky(a4.x + c4.x), h1 = leaky(a4.y + c4.y);
        float h2 = leaky(a4.z + c4.z), h3 = leaky(a4.w + c4.w);
        unsigned p0, l0, p1, l1;
        split2(h0, h1, p0, l0);
        split2(h2, h3, p1, l1);
        hh[m*68 + lane*2]     = p0;
        hh[m*68 + lane*2 + 1] = p1;
        hl[m*68 + lane*2]     = l0;
        hl[m*68 + lane*2 + 1] = l1;
    }
    __syncwarp();

    float acc[8][4];
    #pragma unroll
    for (int nt = 0; nt < 8; nt++)
        #pragma unroll
        for (int i = 0; i < 4; i++) acc[nt][i] = 0.f;

    int r = lane >> 2, q = lane & 3;
    #pragma unroll
    for (int kb = 0; kb < 8; kb++){
        unsigned ah[4], al[4];
        ah[0] = hh[r*68 + kb*8 + q];       al[0] = hl[r*68 + kb*8 + q];
        ah[1] = hh[(r+8)*68 + kb*8 + q];   al[1] = hl[(r+8)*68 + kb*8 + q];
        ah[2] = hh[r*68 + kb*8 + 4 + q];   al[2] = hl[r*68 + kb*8 + 4 + q];
        ah[3] = hh[(r+8)*68 + kb*8 + 4+q]; al[3] = hl[(r+8)*68 + kb*8 + 4+q];
        #pragma unroll
        for (int nt = 0; nt < 8; nt++){
            uint4 wv = __ldg(&g_w2bpb[(kb*8 + nt)*32 + lane]);
            unsigned bh[2] = {wv.x, wv.y};
            unsigned bl[2] = {wv.z, wv.w};
            mma16(acc[nt], ah, bh);
            mma16(acc[nt], ah, bl);
            mma16(acc[nt], al, bh);
        }
    }

    #pragma unroll
    for (int nt = 0; nt < 8; nt++){
        float m0 = fmaxf(acc[nt][0], acc[nt][2]);
        float m1 = fmaxf(acc[nt][1], acc[nt][3]);
        #pragma unroll
        for (int off = 4; off < 32; off <<= 1){
            m0 = fmaxf(m0, __shfl_xor_sync(0xffffffffu, m0, off));
            m1 = fmaxf(m1, __shfl_xor_sync(0xffffffffu, m1, off));
        }
        if (lane < 4){
            int c = nt*8 + lane*2;
            g_x2[(size_t)node*64 + c]     = leaky(m0 + __ldg(bias + c));
            g_x2[(size_t)node*64 + c + 1] = leaky(m1 + __ldg(bias + c + 1));
        }
    }
}

__device__ __forceinline__ float featval(int node, int d){
    if (d < 5)   return g_xx[node*5 + d];
    if (d < 69)  return g_x1[(size_t)node*64 + d - 5];
    if (d < 133) return g_x2[(size_t)node*64 + d - 69];
    return 0.f;
}

// ---------------- 4a) lin1: [BN x 144] @ [144 x 512] + leaky (bf16) ----------
__global__ void k_lin1(const float* __restrict__ bl1){
    __shared__ unsigned CSh[64*76];
    __shared__ unsigned CSl[64*76];
    int t = threadIdx.x, lane = t & 31, w = t >> 5;
    int base = blockIdx.x*64;
    for (int i = t; i < 64*72; i += 256){
        int m = i / 72, p = i - m*72;
        int node = base + m;
        float v0 = featval(node, 2*p);
        float v1 = featval(node, 2*p + 1);
        unsigned h, l;
        split2(v0, v1, h, l);
        CSh[m*76 + p] = h;
        CSl[m*76 + p] = l;
    }
    __syncthreads();

    int r = lane >> 2, q = lane & 3;
    int n0 = w*64;
    for (int np = 0; np < 2; np++){
        float acc[4][4][4];
        #pragma unroll
        for (int mt = 0; mt < 4; mt++)
            #pragma unroll
            for (int nt = 0; nt < 4; nt++)
                #pragma unroll
                for (int i = 0; i < 4; i++) acc[mt][nt][i] = 0.f;

        for (int kb = 0; kb < 9; kb++){
            unsigned ah[4][4], al[4][4];
            #pragma unroll
            for (int mt = 0; mt < 4; mt++){
                int rb = mt*16;
                ah[mt][0] = CSh[(rb+r)*76 + kb*8 + q];       al[mt][0] = CSl[(rb+r)*76 + kb*8 + q];
                ah[mt][1] = CSh[(rb+r+8)*76 + kb*8 + q];     al[mt][1] = CSl[(rb+r+8)*76 + kb*8 + q];
                ah[mt][2] = CSh[(rb+r)*76 + kb*8 + 4 + q];   al[mt][2] = CSl[(rb+r)*76 + kb*8 + 4 + q];
                ah[mt][3] = CSh[(rb+r+8)*76 + kb*8 + 4 + q]; al[mt][3] = CSl[(rb+r+8)*76 + kb*8 + 4 + q];
            }
            #pragma unroll
            for (int nt = 0; nt < 4; nt++){
                uint4 wv = __ldg(&g_wl1pb[(kb*64 + w*8 + np*4 + nt)*32 + lane]);
                unsigned bh[2] = {wv.x, wv.y};
                unsigned bl[2] = {wv.z, wv.w};
                #pragma unroll
                for (int mt = 0; mt < 4; mt++){
                    mma16(acc[mt][nt], ah[mt], bh);
                    mma16(acc[mt][nt], ah[mt], bl);
                    mma16(acc[mt][nt], al[mt], bh);
                }
            }
        }
        #pragma unroll
        for (int mt = 0; mt < 4; mt++){
            #pragma unroll
            for (int nt = 0; nt < 4; nt++){
                int node = base + mt*16 + r;
                int col = n0 + (np*4 + nt)*8 + q*2;
                float b0 = __ldg(bl1 + col), b1 = __ldg(bl1 + col + 1);
                float2 u0, u1;
                u0.x = leaky(acc[mt][nt][0] + b0); u0.y = leaky(acc[mt][nt][1] + b1);
                u1.x = leaky(acc[mt][nt][2] + b0); u1.y = leaky(acc[mt][nt][3] + b1);
                *(float2*)(g_d2 + (size_t)node*512 + col)     = u0;
                *(float2*)(g_d2 + (size_t)(node+8)*512 + col) = u1;
            }
        }
    }
}

// ---------------- 4b) lin2: [BN x 512] @ [512 x 256] + max-pool (bf16) -------
__global__ void k_lin2(const float* __restrict__ bl2){
    __shared__ unsigned Ash[64*36];
    __shared__ unsigned Asl[64*36];
    int t = threadIdx.x, lane = t & 31, w = t >> 5;
    int base = blockIdx.x*64;
    int g = base / NN;
    int r = lane >> 2, q = lane & 3;
    int n0 = w*32;

    float acc[4][4][4];
    #pragma unroll
    for (int mt = 0; mt < 4; mt++)
        #pragma unroll
        for (int nt = 0; nt < 4; nt++)
            #pragma unroll
            for (int i = 0; i < 4; i++) acc[mt][nt][i] = 0.f;

    for (int kc = 0; kc < 512; kc += 64){
        __syncthreads();
        for (int i = t; i < 1024; i += 256){
            int m = i >> 4, sub = i & 15;
            float4 v = *(const float4*)(g_d2 + (size_t)(base + m)*512 + kc + sub*4);
            unsigned h0, l0, h1, l1;
            split2(v.x, v.y, h0, l0);
            split2(v.z, v.w, h1, l1);
            Ash[m*36 + sub*2]     = h0;
            Ash[m*36 + sub*2 + 1] = h1;
            Asl[m*36 + sub*2]     = l0;
            Asl[m*36 + sub*2 + 1] = l1;
        }
        __syncthreads();
        #pragma unroll
        for (int kb = 0; kb < 4; kb++){
            unsigned ah[4][4], al[4][4];
            #pragma unroll
            for (int mt = 0; mt < 4; mt++){
                int rb = mt*16;
                ah[mt][0] = Ash[(rb+r)*36 + kb*8 + q];       al[mt][0] = Asl[(rb+r)*36 + kb*8 + q];
                ah[mt][1] = Ash[(rb+r+8)*36 + kb*8 + q];     al[mt][1] = Asl[(rb+r+8)*36 + kb*8 + q];
                ah[mt][2] = Ash[(rb+r)*36 + kb*8 + 4 + q];   al[mt][2] = Asl[(rb+r)*36 + kb*8 + 4 + q];
                ah[mt][3] = Ash[(rb+r+8)*36 + kb*8 + 4 + q]; al[mt][3] = Asl[(rb+r+8)*36 + kb*8 + 4 + q];
            }
            int kbg = (kc >> 4) + kb;
            #pragma unroll
            for (int nt = 0; nt < 4; nt++){
                uint4 wv = __ldg(&g_wl2pb[(kbg*32 + w*4 + nt)*32 + lane]);
                unsigned bh[2] = {wv.x, wv.y};
                unsigned bl[2] = {wv.z, wv.w};
                #pragma unroll
                for (int mt = 0; mt < 4; mt++){
                    mma16(acc[mt][nt], ah[mt], bh);
                    mma16(acc[mt][nt], ah[mt], bl);
                    mma16(acc[mt][nt], al[mt], bh);
                }
            }
        }
    }

    #pragma unroll
    for (int nt = 0; nt < 4; nt++){
        float m0 = -3.4e38f, m1 = -3.4e38f;
        #pragma unroll
        for (int mt = 0; mt < 4; mt++){
            m0 = fmaxf(m0, fmaxf(acc[mt][nt][0], acc[mt][nt][2]));
            m1 = fmaxf(m1, fmaxf(acc[mt][nt][1], acc[mt][nt][3]));
        }
        #pragma unroll
        for (int off = 4; off < 32; off <<= 1){
            m0 = fmaxf(m0, __shfl_xor_sync(0xffffffffu, m0, off));
            m1 = fmaxf(m1, __shfl_xor_sync(0xffffffffu, m1, off));
        }
        if (lane < 4){
            int col = n0 + nt*8 + lane*2;
            atomicMaxFloat(&g_pool[g*256 + col],     m0 + __ldg(bl2 + col));
            atomicMaxFloat(&g_pool[g*256 + col + 1], m1 + __ldg(bl2 + col + 1));
        }
    }
}

// ---------------- 5) head: leaky -> 256x128 -> leaky -> 128x3 ----------------
__global__ void k_head(const float* __restrict__ wm1, const float* __restrict__ bm1,
                       const float* __restrict__ wm2, const float* __restrict__ bm2,
                       float* __restrict__ out){
    __shared__ float gs[256];
    __shared__ float ms[128];
    int b = blockIdx.x, t = threadIdx.x;
    for (int c = t; c < 256; c += 128) gs[c] = leaky(g_pool[b*256 + c]);
    __syncthreads();
    float acc = bm1[t];
    #pragma unroll 8
    for (int d = 0; d < 256; d++) acc += gs[d]*wm1[d*128 + t];
    ms[t] = leaky(acc);
    __syncthreads();
    if (t < 3){
        float o = bm2[t];
        #pragma unroll 8
        for (int d = 0; d < 128; d++) o += ms[d]*wm2[d*3 + t];
        out[b*3 + t] = o;
    }
}

// -----------------------------------------------------------------------------
extern "C" void kernel_launch(void* const* d_in, const int* in_sizes, int n_in,
                              void* d_out, int out_size){
    const float* x   = (const float*)d_in[0];
    const float* pos = (const float*)d_in[1];
    const float* tq  = (const float*)d_in[2];
    const float* w1a = (const float*)d_in[4];
    const float* b1a = (const float*)d_in[5];
    const float* w1b = (const float*)d_in[6];
    const float* b1b = (const float*)d_in[7];
    const float* w2a = (const float*)d_in[8];
    const float* b2a = (const float*)d_in[9];
    const float* w2b = (const float*)d_in[10];
    const float* b2b = (const float*)d_in[11];
    const float* wl1 = (const float*)d_in[12];
    const float* bl1 = (const float*)d_in[13];
    const float* wl2 = (const float*)d_in[14];
    const float* bl2 = (const float*)d_in[15];
    const float* wm1 = (const float*)d_in[16];
    const float* bm1 = (const float*)d_in[17];
    const float* wm2 = (const float*)d_in[18];
    const float* bm2 = (const float*)d_in[19];
    float* out = (float*)d_out;

    k_prep<<<216, 256>>>(w1b, w2b, wl1, wl2);
    k_build<<<BN/256, 256>>>(x, pos, tq);

    // conv1
    k_knn5<<<BATCH*(NN/8), 256>>>();
    k_convA1<<<(BN*64)/256, 256>>>(w1a, b1a);
    k_edge64<<<BN/4, 128>>>(b1b);        // also emits g_sq

    // conv2
    {
        dim3 grid(4, 4, BATCH);
        k_d2t<<<grid, 256>>>();
    }
    k_select<<<BN/8, 256>>>();
    k_convA2<<<BN/16, 256>>>(w2a, b2a);
    k_edge128<<<BN/4, 128>>>(b2b);

    // lin1 -> g_d2 (HS), lin2 + fused pool, head
    k_lin1<<<BN/64, 256>>>(bl1);
    k_lin2<<<BN/64, 256>>>(bl2);
    k_head<<<BATCH, 128>>>(wm1, bm1, wm2, bm2, out);
}

// round 9
// speedup vs baseline: 1.7995x; 1.0057x over previous
#include <cuda_runtime.h>
#include <cuda_bf16.h>
#include <cstdint>

#define BATCH 128
#define NN    512
#define KNB   16
#define BN    (BATCH*NN)
#define NEGS  0.01f

// ---------------- scratch (device globals; no allocation allowed) -------------
__device__ float g_xx[BN*5];
__device__ float g_x1[BN*64];
__device__ float g_x2[BN*64];
__device__ int   g_idx[BN*KNB];
__device__ float g_A[(size_t)BN*128];
__device__ float g_C[(size_t)BN*128];
__device__ float g_pool[BATCH*256];
__device__ float g_sq[BN];
__device__ float g_sq5[BN];
__device__ float g_d2[(size_t)BN*NN];   // d2 matrix, later reused as HS buffer

// W^T A-operand fragment tables for edge kernels (indexed (mt*8+kb)*32+lane)
__device__ uint4 g_w1Ah[1024], g_w1Al[1024];   // conv1 W2 (64x64), tf32 split
__device__ uint4 g_w2Ah[1024], g_w2Al[1024];   // conv2 W2 (128x64), bf16 split
// bf16 split fragment-packed B-operand weights for lin kernels
__device__ uint4  g_wl1pb[9*64*32];      // 144x512 (rows >=133 zero)
__device__ uint4  g_wl2pb[32*32*32];     // 512x256

__device__ __forceinline__ float leaky(float v){ return v > 0.f ? v : NEGS*v; }

__device__ __forceinline__ void atomicMaxFloat(float* addr, float value){
    if (value >= 0.f) atomicMax((int*)addr, __float_as_int(value));
    else              atomicMin((unsigned int*)addr, __float_as_uint(value));
}

__device__ __forceinline__ unsigned f2tf(float x){
    unsigned u; asm("cvt.rna.tf32.f32 %0, %1;" : "=r"(u) : "f"(x)); return u;
}
__device__ __forceinline__ void splt(float x, unsigned &h, unsigned &l){
    h = f2tf(x);
    l = f2tf(x - __uint_as_float(h));
}
__device__ __forceinline__ void mma8(float* c, const unsigned* a, const unsigned* b){
    asm("mma.sync.aligned.m16n8k8.row.col.f32.tf32.tf32.f32 "
        "{%0,%1,%2,%3}, {%4,%5,%6,%7}, {%8,%9}, {%0,%1,%2,%3};"
        : "+f"(c[0]), "+f"(c[1]), "+f"(c[2]), "+f"(c[3])
        : "r"(a[0]), "r"(a[1]), "r"(a[2]), "r"(a[3]), "r"(b[0]), "r"(b[1]));
}
__device__ __forceinline__ void mma16(float* c, const unsigned* a, const unsigned* b){
    asm("mma.sync.aligned.m16n8k16.row.col.f32.bf16.bf16.f32 "
        "{%0,%1,%2,%3}, {%4,%5,%6,%7}, {%8,%9}, {%0,%1,%2,%3};"
        : "+f"(c[0]), "+f"(c[1]), "+f"(c[2]), "+f"(c[3])
        : "r"(a[0]), "r"(a[1]), "r"(a[2]), "r"(a[3]), "r"(b[0]), "r"(b[1]));
}
// pack (v0 -> low bf16, v1 -> high bf16)
__device__ __forceinline__ unsigned packbf(float v0, float v1){
    unsigned d; asm("cvt.rn.bf16x2.f32 %0, %1, %2;" : "=r"(d) : "f"(v1), "f"(v0)); return d;
}
__device__ __forceinline__ float bflo(unsigned p){ return __uint_as_float(p << 16); }
__device__ __forceinline__ float bfhi(unsigned p){ return __uint_as_float(p & 0xffff0000u); }
__device__ __forceinline__ void split2(float v0, float v1, unsigned &h, unsigned &l){
    h = packbf(v0, v1);
    l = packbf(v0 - bflo(h), v1 - bfhi(h));
}

// sortable-u32 transform
__device__ __forceinline__ unsigned fsort(float f){
    unsigned b = __float_as_uint(f);
    return b ^ (((int)b >> 31) | 0x80000000u);
}

// warp-cooperative exact top-16-of-512 with lower-index tiebreak.
template<bool LANEMAJOR>
__device__ __forceinline__ void sel16(const float* v, int lane, int* out){
    const unsigned long long INF = ~0ull;
    unsigned long long s0 = INF, s1 = INF, s2 = INF, s3 = INF;
    #pragma unroll
    for (int u = 0; u < 16; u++){
        int j = LANEMAJOR ? (lane*16 + u) : (u*32 + lane);
        unsigned long long k = ((unsigned long long)fsort(v[u]) << 32) | (unsigned)j;
        if (k < s3){
            s3 = k;
            if (s3 < s2){ unsigned long long t = s2; s2 = s3; s3 = t; }
            if (s2 < s1){ unsigned long long t = s1; s1 = s2; s2 = t; }
            if (s1 < s0){ unsigned long long t = s0; s0 = s1; s1 = t; }
        }
    }
    unsigned mask = 0;
    int mine = 0;
    #pragma unroll 1
    for (int r = 0; r < KNB; r++){
        unsigned long long m = s0;
        #pragma unroll
        for (int off = 16; off; off >>= 1){
            unsigned long long o = __shfl_xor_sync(0xffffffffu, m, off);
            if (o < m) m = o;
        }
        if (lane == r) mine = (int)(unsigned)(m & 0xffffffffu);
        if (s0 == m){
            int j = (int)(unsigned)(m & 0xffffffffu);
            int u = LANEMAJOR ? (j & 15) : (j >> 5);
            mask |= 1u << u;
            s0 = s1; s1 = s2; s2 = s3; s3 = INF;
            if (s0 == INF && mask != 0xffffu){
                #pragma unroll
                for (int u2 = 0; u2 < 16; u2++){
                    if (!((mask >> u2) & 1u)){
                        int j2 = LANEMAJOR ? (lane*16 + u2) : (u2*32 + lane);
                        unsigned long long k = ((unsigned long long)fsort(v[u2]) << 32) | (unsigned)j2;
                        if (k < s3){
                            s3 = k;
                            if (s3 < s2){ unsigned long long t = s2; s2 = s3; s3 = t; }
                            if (s2 < s1){ unsigned long long t = s1; s1 = s2; s2 = t; }
                            if (s1 < s0){ unsigned long long t = s0; s0 = s1; s1 = t; }
                        }
                    }
                }
            }
        }
    }
    if (lane < KNB) out[lane] = mine;
}

// ---------------- prep: pool init + pack all weight fragment tables ----------
__global__ void k_prep(const float* __restrict__ w1b, const float* __restrict__ w2b,
                       const float* __restrict__ wl1, const float* __restrict__ wl2){
    int i = blockIdx.x*256 + threadIdx.x;
    if (i < BATCH*256) g_pool[i] = __int_as_float(0xff800000); // -inf

    if (i < 1024){
        // conv1 W2^T as tf32 A-fragments: a0=(r,q) a1=(r+8,q) a2=(r,q+4) a3=(r+8,q+4)
        int lane = i & 31, tmp = i >> 5;
        int kb = tmp & 7, mt = tmp >> 3;
        int r = lane >> 2, q = lane & 3;
        int R = mt*16 + r, k0 = kb*8 + q;
        float v0 = w1b[k0*64 + R];
        float v1 = w1b[k0*64 + R + 8];
        float v2 = w1b[(k0+4)*64 + R];
        float v3 = w1b[(k0+4)*64 + R + 8];
        uint4 H, L;
        splt(v0, H.x, L.x); splt(v1, H.y, L.y);
        splt(v2, H.z, L.z); splt(v3, H.w, L.w);
        g_w1Ah[i] = H; g_w1Al[i] = L;
    } else if (i < 2048){
        // conv2 W2^T as bf16 A-fragments: a0=(r, 2q..2q+1) a1=(r+8,..) a2=(r, 8+2q..) a3=(r+8,..)
        int rel = i - 1024;
        int lane = rel & 31, tmp = rel >> 5;
        int kb = tmp & 7, mt = tmp >> 3;
        int r = lane >> 2, q = lane & 3;
        int R = mt*16 + r, c0 = kb*16 + 2*q;
        uint4 H, L;
        split2(w2b[c0*64 + R],       w2b[(c0+1)*64 + R],       H.x, L.x);
        split2(w2b[c0*64 + R + 8],   w2b[(c0+1)*64 + R + 8],   H.y, L.y);
        split2(w2b[(c0+8)*64 + R],   w2b[(c0+9)*64 + R],       H.z, L.z);
        split2(w2b[(c0+8)*64 + R+8], w2b[(c0+9)*64 + R + 8],   H.w, L.w);
        g_w2Ah[rel] = H; g_w2Al[rel] = L;
    } else if (i < 53248){
        const float* W; uint4* dst; int ncb, ncols, nrows, rel;
        if (i < 20480){ rel = i - 2048;  W = wl1; dst = g_wl1pb; ncb = 64; ncols = 512; nrows = 133; }
        else          { rel = i - 20480; W = wl2; dst = g_wl2pb; ncb = 32; ncols = 256; nrows = 512; }
        int lane = rel & 31, tmp = rel >> 5;
        int cb = tmp % ncb, kb = tmp / ncb;
        int r = lane >> 2, q = lane & 3, col = cb*8 + r;
        int k0 = kb*16 + 2*q;
        float v00 = (k0     < nrows) ? W[(k0    )*ncols + col] : 0.f;
        float v01 = (k0 + 1 < nrows) ? W[(k0 + 1)*ncols + col] : 0.f;
        float v10 = (k0 + 8 < nrows) ? W[(k0 + 8)*ncols + col] : 0.f;
        float v11 = (k0 + 9 < nrows) ? W[(k0 + 9)*ncols + col] : 0.f;
        unsigned h0, l0, h1, l1;
        split2(v00, v01, h0, l0);
        split2(v10, v11, h1, l1);
        dst[rel] = make_uint4(h0, h1, l0, l1);
    }
}

// ---------------- 0) build xx = [tq, x, pos] + 5d norms ----------------------
__global__ void k_build(const float* __restrict__ x, const float* __restrict__ pos,
                        const float* __restrict__ tq){
    int i = blockIdx.x*blockDim.x + threadIdx.x;
    if (i < BN){
        float tv = tq[i], xv = x[i];
        float p0 = pos[i*3+0], p1 = pos[i*3+1], p2 = pos[i*3+2];
        g_xx[i*5+0] = tv;
        g_xx[i*5+1] = xv;
        g_xx[i*5+2] = p0;
        g_xx[i*5+3] = p1;
        g_xx[i*5+4] = p2;
        g_sq5[i] = tv*tv + xv*xv + p0*p0 + p1*p1 + p2*p2;
    }
}

// ---------------- 1a) kNN d=5 ------------------------------------------------
__global__ void k_knn5(){
    __shared__ float tile[128*8];    // c0..4 = feat, c5 = sq, c6..7 pad
    int b  = blockIdx.x >> 6;
    int q0 = (blockIdx.x & 63) * 8;
    int warp = threadIdx.x >> 5, lane = threadIdx.x & 31;
    int qi = q0 + warp;
    int node = b*NN + qi;
    const float* Fb = g_xx + (size_t)b*NN*5;

    float f0, f1, f2, f3, f4;
    { const float* fq = Fb + qi*5; f0=fq[0]; f1=fq[1]; f2=fq[2]; f3=fq[3]; f4=fq[4]; }
    float sqi = g_sq5[node];

    float d2loc[16];
    for (int t4 = 0; t4 < 4; t4++){
        __syncthreads();
        for (int idx = threadIdx.x; idx < 1024; idx += 256){
            int rrow = idx >> 3, c = idx & 7;
            int grow = t4*128 + rrow;
            float v = 0.f;
            if (c < 5)       v = Fb[grow*5 + c];
            else if (c == 5) v = g_sq5[b*NN + grow];
            tile[idx] = v;
        }
        __syncthreads();
        #pragma unroll
        for (int u = 0; u < 4; u++){
            int jj = u*32 + lane;
            const float* tr = &tile[jj*8];
            float4 p  = *(const float4*)tr;
            float2 p2 = *(const float2*)(tr + 4);
            float dot = f0*p.x + f1*p.y + f2*p.z + f3*p.w + f4*p2.x;
            d2loc[t4*4 + u] = sqi + p2.y - 2.f*dot;
        }
    }
    sel16<false>(d2loc, lane, g_idx + (size_t)node*KNB);
}

// ---------------- 1c) kNN d=64: pairwise d2 via split-TF32 mma ---------------
__global__ void k_d2t(){
    __shared__ float As[128*36];
    __shared__ float Bs[128*36];
    int b  = blockIdx.z;
    int i0 = blockIdx.y*128, j0 = blockIdx.x*128;
    const float* Fb = g_x1 + (size_t)b*NN*64;
    int t = threadIdx.x, lane = t & 31, w = t >> 5;
    int wx = w & 1, wy = w >> 1;
    int r = lane >> 2, q = lane & 3;

    float acc[2][8][4];
    #pragma unroll
    for (int mt = 0; mt < 2; mt++)
        #pragma unroll
        for (int nt = 0; nt < 8; nt++)
            #pragma unroll
            for (int i = 0; i < 4; i++) acc[mt][nt][i] = 0.f;

    for (int kc = 0; kc < 64; kc += 32){
        __syncthreads();
        for (int i = t; i < 128*8; i += 256){
            int m = i >> 3, kq = (i & 7)*4;
            *(float4*)&As[m*36 + kq] = *(const float4*)(Fb + (i0+m)*64 + kc + kq);
            *(float4*)&Bs[m*36 + kq] = *(const float4*)(Fb + (j0+m)*64 + kc + kq);
        }
        __syncthreads();
        #pragma unroll
        for (int k0 = 0; k0 < 32; k0 += 8){
            unsigned ah[2][4], al[2][4];
            #pragma unroll
            for (int mt = 0; mt < 2; mt++){
                int row = wy*32 + mt*16;
                splt(As[(row+r)*36 + k0 + q],       ah[mt][0], al[mt][0]);
                splt(As[(row+r+8)*36 + k0 + q],     ah[mt][1], al[mt][1]);
                splt(As[(row+r)*36 + k0 + q + 4],   ah[mt][2], al[mt][2]);
                splt(As[(row+r+8)*36 + k0 + q + 4], ah[mt][3], al[mt][3]);
            }
            #pragma unroll
            for (int nt = 0; nt < 8; nt++){
                int col = wx*64 + nt*8;
                unsigned bh[2], bl[2];
                splt(Bs[(col+r)*36 + k0 + q],     bh[0], bl[0]);
                splt(Bs[(col+r)*36 + k0 + q + 4], bh[1], bl[1]);
                #pragma unroll
                for (int mt = 0; mt < 2; mt++){
                    mma8(acc[mt][nt], ah[mt], bh);
                    mma8(acc[mt][nt], ah[mt], bl);
                    mma8(acc[mt][nt], al[mt], bh);
                }
            }
        }
    }

    #pragma unroll
    for (int mt = 0; mt < 2; mt++){
        int rowb = i0 + wy*32 + mt*16;
        float si0 = g_sq[b*NN + rowb + r];
        float si1 = g_sq[b*NN + rowb + r + 8];
        #pragma unroll
        for (int nt = 0; nt < 8; nt++){
            int colb = j0 + wx*64 + nt*8 + 2*q;
            float sj0 = g_sq[b*NN + colb], sj1 = g_sq[b*NN + colb + 1];
            float2 v0, v1;
            v0.x = si0 + sj0 - 2.f*acc[mt][nt][0];
            v0.y = si0 + sj1 - 2.f*acc[mt][nt][1];
            v1.x = si1 + sj0 - 2.f*acc[mt][nt][2];
            v1.y = si1 + sj1 - 2.f*acc[mt][nt][3];
            *(float2*)(g_d2 + (size_t)(b*NN + rowb + r)*NN + colb)     = v0;
            *(float2*)(g_d2 + (size_t)(b*NN + rowb + r + 8)*NN + colb) = v1;
        }
    }
}

// ---------------- 1d) kNN d=64: cached-top4 select ---------------------------
__global__ void k_select(){
    int warp = threadIdx.x >> 5, lane = threadIdx.x & 31;
    int node = blockIdx.x*8 + warp;
    const float* row = g_d2 + (size_t)node*NN;
    float v[16];
    #pragma unroll
    for (int u4 = 0; u4 < 4; u4++){
        float4 x = *(const float4*)(row + lane*16 + u4*4);
        v[u4*4+0] = x.x; v[u4*4+1] = x.y; v[u4*4+2] = x.z; v[u4*4+3] = x.w;
    }
    sel16<true>(v, lane, g_idx + (size_t)node*KNB);
}

// ---------------- 2a) conv1 layer-1 factorization (d=5, H=64) ----------------
__global__ void k_convA1(const float* __restrict__ W, const float* __restrict__ bias){
    int t = blockIdx.x*blockDim.x + threadIdx.x;
    if (t >= BN*64) return;
    int i = t >> 6, c = t & 63;
    const float* f = g_xx + (size_t)i*5;
    float a = bias[c], cc = 0.f;
    #pragma unroll
    for (int d = 0; d < 5; d++){
        float v  = f[d];
        float wt = W[d*64 + c];
        float wb = W[(5 + d)*64 + c];
        a  += v*(wt - wb);
        cc += v*wb;
    }
    g_A[(size_t)i*64 + c] = a;
    g_C[(size_t)i*64 + c] = cc;
}

// ---------------- 2b) conv2 layer-1 (d=64, H=128) ----------------------------
__global__ void k_convA2(const float* __restrict__ W, const float* __restrict__ bias){
    __shared__ float Wd[32*128];
    __shared__ float Wb[32*128];
    __shared__ float Fs[16*64];
    int t = threadIdx.x;
    int base = blockIdx.x*16;

    for (int idx = t; idx < 1024; idx += 256)
        Fs[idx] = g_x1[(size_t)base*64 + idx];

    int m  = t >> 4;
    int cg = (t & 15)*8;
    float a[8], cc[8];
    float4 bb0 = *(const float4*)(bias + cg);
    float4 bb1 = *(const float4*)(bias + cg + 4);
    a[0]=bb0.x; a[1]=bb0.y; a[2]=bb0.z; a[3]=bb0.w;
    a[4]=bb1.x; a[5]=bb1.y; a[6]=bb1.z; a[7]=bb1.w;
    #pragma unroll
    for (int q = 0; q < 8; q++) cc[q] = 0.f;

    for (int db = 0; db < 64; db += 32){
        __syncthreads();
        for (int idx = t; idx < 4096; idx += 256){
            int d = idx >> 7, c = idx & 127;
            float wt = W[(db + d)*128 + c];
            float wb = W[(64 + db + d)*128 + c];
            Wd[idx] = wt - wb;
            Wb[idx] = wb;
        }
        __syncthreads();
        #pragma unroll 4
        for (int d = 0; d < 32; d++){
            float v = Fs[m*64 + db + d];
            float4 w0 = *(const float4*)&Wd[d*128 + cg];
            float4 w1 = *(const float4*)&Wd[d*128 + cg + 4];
            float4 u0 = *(const float4*)&Wb[d*128 + cg];
            float4 u1 = *(const float4*)&Wb[d*128 + cg + 4];
            a[0] += v*w0.x; a[1] += v*w0.y; a[2] += v*w0.z; a[3] += v*w0.w;
            a[4] += v*w1.x; a[5] += v*w1.y; a[6] += v*w1.z; a[7] += v*w1.w;
            cc[0] += v*u0.x; cc[1] += v*u0.y; cc[2] += v*u0.z; cc[3] += v*u0.w;
            cc[4] += v*u1.x; cc[5] += v*u1.y; cc[6] += v*u1.z; cc[7] += v*u1.w;
        }
    }
    int node = base + m;
    float4* pa = (float4*)(g_A + (size_t)node*128 + cg);
    float4* pc = (float4*)(g_C + (size_t)node*128 + cg);
    pa[0] = make_float4(a[0],a[1],a[2],a[3]);
    pa[1] = make_float4(a[4],a[5],a[6],a[7]);
    pc[0] = make_float4(cc[0],cc[1],cc[2],cc[3]);
    pc[1] = make_float4(cc[4],cc[5],cc[6],cc[7]);
}

// ---------------- 3a) conv1 edge layer-2: D^T = W^T @ h^T (tf32, no smem) ----
// One warp per node; B-fragments built in registers from the gather.
__global__ void k_edge64(const float* __restrict__ bias){
    int t = threadIdx.x, warp = t >> 5, lane = t & 31;
    int node = blockIdx.x*8 + warp;
    int b = node / NN;
    int r = lane >> 2, q = lane & 3;

    int j0 = b*NN + __ldg(g_idx + (size_t)node*KNB + r);
    int j1 = b*NN + __ldg(g_idx + (size_t)node*KNB + 8 + r);
    const float* Ai = g_A + (size_t)node*64;
    const float* C0 = g_C + (size_t)j0*64;
    const float* C1 = g_C + (size_t)j1*64;

    float acc[4][2][4];
    #pragma unroll
    for (int mt = 0; mt < 4; mt++)
        #pragma unroll
        for (int n = 0; n < 2; n++)
            #pragma unroll
            for (int i = 0; i < 4; i++) acc[mt][n][i] = 0.f;

    #pragma unroll
    for (int kb = 0; kb < 8; kb++){
        int c0 = kb*8 + q;
        float ai0 = __ldg(Ai + c0), ai1 = __ldg(Ai + c0 + 4);
        unsigned b0h[2], b0l[2], b1h[2], b1l[2];
        splt(leaky(ai0 + __ldg(C0 + c0)),     b0h[0], b0l[0]);
        splt(leaky(ai1 + __ldg(C0 + c0 + 4)), b0h[1], b0l[1]);
        splt(leaky(ai0 + __ldg(C1 + c0)),     b1h[0], b1l[0]);
        splt(leaky(ai1 + __ldg(C1 + c0 + 4)), b1h[1], b1l[1]);
        #pragma unroll
        for (int mt = 0; mt < 4; mt++){
            uint4 H = __ldg(&g_w1Ah[(mt*8 + kb)*32 + lane]);
            uint4 L = __ldg(&g_w1Al[(mt*8 + kb)*32 + lane]);
            mma8(acc[mt][0], (const unsigned*)&H, b0h);
            mma8(acc[mt][0], (const unsigned*)&H, b0l);
            mma8(acc[mt][0], (const unsigned*)&L, b0h);
            mma8(acc[mt][1], (const unsigned*)&H, b1h);
            mma8(acc[mt][1], (const unsigned*)&H, b1l);
            mma8(acc[mt][1], (const unsigned*)&L, b1h);
        }
    }

    // rows = out channels {mt*16+r, +8}; cols = neighbors {2q, 2q+1} per ntile.
    float ssum = 0.f;
    #pragma unroll
    for (int mt = 0; mt < 4; mt++){
        float m0 = fmaxf(fmaxf(acc[mt][0][0], acc[mt][0][1]),
                         fmaxf(acc[mt][1][0], acc[mt][1][1]));
        float m1 = fmaxf(fmaxf(acc[mt][0][2], acc[mt][0][3]),
                         fmaxf(acc[mt][1][2], acc[mt][1][3]));
        m0 = fmaxf(m0, __shfl_xor_sync(0xffffffffu, m0, 1));
        m0 = fmaxf(m0, __shfl_xor_sync(0xffffffffu, m0, 2));
        m1 = fmaxf(m1, __shfl_xor_sync(0xffffffffu, m1, 1));
        m1 = fmaxf(m1, __shfl_xor_sync(0xffffffffu, m1, 2));
        if (q == 0){
            int ch = mt*16 + r;
            float v0 = leaky(m0 + __ldg(bias + ch));
            float v1 = leaky(m1 + __ldg(bias + ch + 8));
            g_x1[(size_t)node*64 + ch]     = v0;
            g_x1[(size_t)node*64 + ch + 8] = v1;
            ssum += v0*v0 + v1*v1;
        }
    }
    // fused row-norm for kNN2 (only q==0 lanes contributed)
    ssum += __shfl_xor_sync(0xffffffffu, ssum, 4);
    ssum += __shfl_xor_sync(0xffffffffu, ssum, 8);
    ssum += __shfl_xor_sync(0xffffffffu, ssum, 16);
    if (lane == 0) g_sq[node] = ssum;
}

// ---------------- 3b) conv2 edge layer-2: D^T = W^T @ h^T (bf16, no smem) ----
__global__ void k_edge128(const float* __restrict__ bias){
    int t = threadIdx.x, warp = t >> 5, lane = t & 31;
    int node = blockIdx.x*8 + warp;
    int b = node / NN;
    int r = lane >> 2, q = lane & 3;

    int j0 = b*NN + __ldg(g_idx + (size_t)node*KNB + r);
    int j1 = b*NN + __ldg(g_idx + (size_t)node*KNB + 8 + r);
    const float* Ai = g_A + (size_t)node*128;
    const float* C0 = g_C + (size_t)j0*128;
    const float* C1 = g_C + (size_t)j1*128;

    float acc[4][2][4];
    #pragma unroll
    for (int mt = 0; mt < 4; mt++)
        #pragma unroll
        for (int n = 0; n < 2; n++)
            #pragma unroll
            for (int i = 0; i < 4; i++) acc[mt][n][i] = 0.f;

    #pragma unroll
    for (int kb = 0; kb < 8; kb++){
        int c0 = kb*16 + 2*q;
        float2 ai0 = *(const float2*)(Ai + c0);
        float2 ai1 = *(const float2*)(Ai + c0 + 8);
        float2 ca0 = *(const float2*)(C0 + c0);
        float2 ca1 = *(const float2*)(C0 + c0 + 8);
        float2 cb0 = *(const float2*)(C1 + c0);
        float2 cb1 = *(const float2*)(C1 + c0 + 8);
        unsigned b0h[2], b0l[2], b1h[2], b1l[2];
        split2(leaky(ai0.x + ca0.x), leaky(ai0.y + ca0.y), b0h[0], b0l[0]);
        split2(leaky(ai1.x + ca1.x), leaky(ai1.y + ca1.y), b0h[1], b0l[1]);
        split2(leaky(ai0.x + cb0.x), leaky(ai0.y + cb0.y), b1h[0], b1l[0]);
        split2(leaky(ai1.x + cb1.x), leaky(ai1.y + cb1.y), b1h[1], b1l[1]);
        #pragma unroll
        for (int mt = 0; mt < 4; mt++){
            uint4 H = __ldg(&g_w2Ah[(mt*8 + kb)*32 + lane]);
            uint4 L = __ldg(&g_w2Al[(mt*8 + kb)*32 + lane]);
            mma16(acc[mt][0], (const unsigned*)&H, b0h);
            mma16(acc[mt][0], (const unsigned*)&H, b0l);
            mma16(acc[mt][0], (const unsigned*)&L, b0h);
            mma16(acc[mt][1], (const unsigned*)&H, b1h);
            mma16(acc[mt][1], (const unsigned*)&H, b1l);
            mma16(acc[mt][1], (const unsigned*)&L, b1h);
        }
    }

    #pragma unroll
    for (int mt = 0; mt < 4; mt++){
        float m0 = fmaxf(fmaxf(acc[mt][0][0], acc[mt][0][1]),
                         fmaxf(acc[mt][1][0], acc[mt][1][1]));
        float m1 = fmaxf(fmaxf(acc[mt][0][2], acc[mt][0][3]),
                         fmaxf(acc[mt][1][2], acc[mt][1][3]));
        m0 = fmaxf(m0, __shfl_xor_sync(0xffffffffu, m0, 1));
        m0 = fmaxf(m0, __shfl_xor_sync(0xffffffffu, m0, 2));
        m1 = fmaxf(m1, __shfl_xor_sync(0xffffffffu, m1, 1));
        m1 = fmaxf(m1, __shfl_xor_sync(0xffffffffu, m1, 2));
        if (q == 0){
            int ch = mt*16 + r;
            g_x2[(size_t)node*64 + ch]     = leaky(m0 + __ldg(bias + ch));
            g_x2[(size_t)node*64 + ch + 8] = leaky(m1 + __ldg(bias + ch + 8));
        }
    }
}

__device__ __forceinline__ float featval(int node, int d){
    if (d < 5)   return g_xx[node*5 + d];
    if (d < 69)  return g_x1[(size_t)node*64 + d - 5];
    if (d < 133) return g_x2[(size_t)node*64 + d - 69];
    return 0.f;
}

// ---------------- 4a) lin1: [BN x 144] @ [144 x 512] + leaky (bf16) ----------
__global__ void k_lin1(const float* __restrict__ bl1){
    __shared__ unsigned CSh[64*76];
    __shared__ unsigned CSl[64*76];
    int t = threadIdx.x, lane = t & 31, w = t >> 5;
    int base = blockIdx.x*64;
    for (int i = t; i < 64*72; i += 256){
        int m = i / 72, p = i - m*72;
        int node = base + m;
        float v0 = featval(node, 2*p);
        float v1 = featval(node, 2*p + 1);
        unsigned h, l;
        split2(v0, v1, h, l);
        CSh[m*76 + p] = h;
        CSl[m*76 + p] = l;
    }
    __syncthreads();

    int r = lane >> 2, q = lane & 3;
    int n0 = w*64;
    for (int np = 0; np < 2; np++){
        float acc[4][4][4];
        #pragma unroll
        for (int mt = 0; mt < 4; mt++)
            #pragma unroll
            for (int nt = 0; nt < 4; nt++)
                #pragma unroll
                for (int i = 0; i < 4; i++) acc[mt][nt][i] = 0.f;

        for (int kb = 0; kb < 9; kb++){
            unsigned ah[4][4], al[4][4];
            #pragma unroll
            for (int mt = 0; mt < 4; mt++){
                int rb = mt*16;
                ah[mt][0] = CSh[(rb+r)*76 + kb*8 + q];       al[mt][0] = CSl[(rb+r)*76 + kb*8 + q];
                ah[mt][1] = CSh[(rb+r+8)*76 + kb*8 + q];     al[mt][1] = CSl[(rb+r+8)*76 + kb*8 + q];
                ah[mt][2] = CSh[(rb+r)*76 + kb*8 + 4 + q];   al[mt][2] = CSl[(rb+r)*76 + kb*8 + 4 + q];
                ah[mt][3] = CSh[(rb+r+8)*76 + kb*8 + 4 + q]; al[mt][3] = CSl[(rb+r+8)*76 + kb*8 + 4 + q];
            }
            #pragma unroll
            for (int nt = 0; nt < 4; nt++){
                uint4 wv = __ldg(&g_wl1pb[(kb*64 + w*8 + np*4 + nt)*32 + lane]);
                unsigned bh[2] = {wv.x, wv.y};
                unsigned bl[2] = {wv.z, wv.w};
                #pragma unroll
                for (int mt = 0; mt < 4; mt++){
                    mma16(acc[mt][nt], ah[mt], bh);
                    mma16(acc[mt][nt], ah[mt], bl);
                    mma16(acc[mt][nt], al[mt], bh);
                }
            }
        }
        #pragma unroll
        for (int mt = 0; mt < 4; mt++){
            #pragma unroll
            for (int nt = 0; nt < 4; nt++){
                int node = base + mt*16 + r;
                int col = n0 + (np*4 + nt)*8 + q*2;
                float b0 = __ldg(bl1 + col), b1 = __ldg(bl1 + col + 1);
                float2 u0, u1;
                u0.x = leaky(acc[mt][nt][0] + b0); u0.y = leaky(acc[mt][nt][1] + b1);
                u1.x = leaky(acc[mt][nt][2] + b0); u1.y = leaky(acc[mt][nt][3] + b1);
                *(float2*)(g_d2 + (size_t)node*512 + col)     = u0;
                *(float2*)(g_d2 + (size_t)(node+8)*512 + col) = u1;
            }
        }
    }
}

// ---------------- 4b) lin2: [BN x 512] @ [512 x 256] + max-pool (bf16) -------
__global__ void k_lin2(const float* __restrict__ bl2){
    __shared__ unsigned Ash[64*36];
    __shared__ unsigned Asl[64*36];
    int t = threadIdx.x, lane = t & 31, w = t >> 5;
    int base = blockIdx.x*64;
    int g = base / NN;
    int r = lane >> 2, q = lane & 3;
    int n0 = w*32;

    float acc[4][4][4];
    #pragma unroll
    for (int mt = 0; mt < 4; mt++)
        #pragma unroll
        for (int nt = 0; nt < 4; nt++)
            #pragma unroll
            for (int i = 0; i < 4; i++) acc[mt][nt][i] = 0.f;

    for (int kc = 0; kc < 512; kc += 64){
        __syncthreads();
        for (int i = t; i < 1024; i += 256){
            int m = i >> 4, sub = i & 15;
            float4 v = *(const float4*)(g_d2 + (size_t)(base + m)*512 + kc + sub*4);
            unsigned h0, l0, h1, l1;
            split2(v.x, v.y, h0, l0);
            split2(v.z, v.w, h1, l1);
            Ash[m*36 + sub*2]     = h0;
            Ash[m*36 + sub*2 + 1] = h1;
            Asl[m*36 + sub*2]     = l0;
            Asl[m*36 + sub*2 + 1] = l1;
        }
        __syncthreads();
        #pragma unroll
        for (int kb = 0; kb < 4; kb++){
            unsigned ah[4][4], al[4][4];
            #pragma unroll
            for (int mt = 0; mt < 4; mt++){
                int rb = mt*16;
                ah[mt][0] = Ash[(rb+r)*36 + kb*8 + q];       al[mt][0] = Asl[(rb+r)*36 + kb*8 + q];
                ah[mt][1] = Ash[(rb+r+8)*36 + kb*8 + q];     al[mt][1] = Asl[(rb+r+8)*36 + kb*8 + q];
                ah[mt][2] = Ash[(rb+r)*36 + kb*8 + 4 + q];   al[mt][2] = Asl[(rb+r)*36 + kb*8 + 4 + q];
                ah[mt][3] = Ash[(rb+r+8)*36 + kb*8 + 4 + q]; al[mt][3] = Asl[(rb+r+8)*36 + kb*8 + 4 + q];
            }
            int kbg = (kc >> 4) + kb;
            #pragma unroll
            for (int nt = 0; nt < 4; nt++){
                uint4 wv = __ldg(&g_wl2pb[(kbg*32 + w*4 + nt)*32 + lane]);
                unsigned bh[2] = {wv.x, wv.y};
                unsigned bl[2] = {wv.z, wv.w};
                #pragma unroll
                for (int mt = 0; mt < 4; mt++){
                    mma16(acc[mt][nt], ah[mt], bh);
                    mma16(acc[mt][nt], ah[mt], bl);
                    mma16(acc[mt][nt], al[mt], bh);
                }
            }
        }
    }

    #pragma unroll
    for (int nt = 0; nt < 4; nt++){
        float m0 = -3.4e38f, m1 = -3.4e38f;
        #pragma unroll
        for (int mt = 0; mt < 4; mt++){
            m0 = fmaxf(m0, fmaxf(acc[mt][nt][0], acc[mt][nt][2]));
            m1 = fmaxf(m1, fmaxf(acc[mt][nt][1], acc[mt][nt][3]));
        }
        #pragma unroll
        for (int off = 4; off < 32; off <<= 1){
            m0 = fmaxf(m0, __shfl_xor_sync(0xffffffffu, m0, off));
            m1 = fmaxf(m1, __shfl_xor_sync(0xffffffffu, m1, off));
        }
        if (lane < 4){
            int col = n0 + nt*8 + lane*2;
            atomicMaxFloat(&g_pool[g*256 + col],     m0 + __ldg(bl2 + col));
            atomicMaxFloat(&g_pool[g*256 + col + 1], m1 + __ldg(bl2 + col + 1));
        }
    }
}

// ---------------- 5) head: leaky -> 256x128 -> leaky -> 128x3 ----------------
__global__ void k_head(const float* __restrict__ wm1, const float* __restrict__ bm1,
                       const float* __restrict__ wm2, const float* __restrict__ bm2,
                       float* __restrict__ out){
    __shared__ float gs[256];
    __shared__ float ms[128];
    int b = blockIdx.x, t = threadIdx.x;
    for (int c = t; c < 256; c += 128) gs[c] = leaky(g_pool[b*256 + c]);
    __syncthreads();
    float acc = bm1[t];
    #pragma unroll 8
    for (int d = 0; d < 256; d++) acc += gs[d]*wm1[d*128 + t];
    ms[t] = leaky(acc);
    __syncthreads();
    if (t < 3){
        float o = bm2[t];
        #pragma unroll 8
        for (int d = 0; d < 128; d++) o += ms[d]*wm2[d*3 + t];
        out[b*3 + t] = o;
    }
}

// -----------------------------------------------------------------------------
extern "C" void kernel_launch(void* const* d_in, const int* in_sizes, int n_in,
                              void* d_out, int out_size){
    const float* x   = (const float*)d_in[0];
    const float* pos = (const float*)d_in[1];
    const float* tq  = (const float*)d_in[2];
    const float* w1a = (const float*)d_in[4];
    const float* b1a = (const float*)d_in[5];
    const float* w1b = (const float*)d_in[6];
    const float* b1b = (const float*)d_in[7];
    const float* w2a = (const float*)d_in[8];
    const float* b2a = (const float*)d_in[9];
    const float* w2b = (const float*)d_in[10];
    const float* b2b = (const float*)d_in[11];
    const float* wl1 = (const float*)d_in[12];
    const float* bl1 = (const float*)d_in[13];
    const float* wl2 = (const float*)d_in[14];
    const float* bl2 = (const float*)d_in[15];
    const float* wm1 = (const float*)d_in[16];
    const float* bm1 = (const float*)d_in[17];
    const float* wm2 = (const float*)d_in[18];
    const float* bm2 = (const float*)d_in[19];
    float* out = (float*)d_out;

    k_prep<<<208, 256>>>(w1b, w2b, wl1, wl2);
    k_build<<<BN/256, 256>>>(x, pos, tq);

    // conv1
    k_knn5<<<BATCH*(NN/8), 256>>>();
    k_convA1<<<(BN*64)/256, 256>>>(w1a, b1a);
    k_edge64<<<BN/8, 256>>>(b1b);        // also emits g_sq

    // conv2
    {
        dim3 grid(4, 4, BATCH);
        k_d2t<<<grid, 256>>>();
    }
    k_select<<<BN/8, 256>>>();
    k_convA2<<<BN/16, 256>>>(w2a, b2a);
    k_edge128<<<BN/8, 256>>>(b2b);

    // lin1 -> g_d2 (HS), lin2 + fused pool, head
    k_lin1<<<BN/64, 256>>>(bl1);
    k_lin2<<<BN/64, 256>>>(bl2);
    k_head<<<BATCH, 128>>>(wm1, bm1, wm2, bm2, out);
}